// round 10
// baseline (speedup 1.0000x reference)
#include <cuda_runtime.h>
#include <cuda_fp16.h>
#include <cstdint>
#include <cstddef>

// Problem: B=4, T=1024, E=4, C=512, i=512, IN=2048, OUT=8192
//   w[e,o,j] = weight_flat[e*4194304 + o*512 + j]   (torch-style reshape)
//   Xd[b,e] = mask[b,:,e,:]^T @ x[b,:,e*512:]        (fp16 MMA, half out)
//   Zh[b,:,e*512:] = cmb[b,:,e,:] @ Xd[b,e]          (fp16 MMA, half out)
//   out[b] = Zh[b] @ Wh^T + bias (x) rowsum(cmb)     (fp16 MMA, M=4096,N=8192,K=2048)

// ---------------- scratch (allocation-free rule) ----------------
static __device__ __half g_xh[4ull * 1024 * 2048];     // 16.8 MB
static __device__ __half g_mh[4ull * 1024 * 4 * 512];  // 16.8 MB
static __device__ __half g_ch[4ull * 1024 * 4 * 512];  // 16.8 MB
static __device__ __half g_Xd[4ull * 4 * 512 * 512];   // 8 MB
static __device__ __half g_Zh[4096ull * 2048];         // 16 MB
static __device__ __half g_Wh[8192ull * 2048];         // 32 MB (permuted half weight)
static __device__ float  g_S [4 * 1024];

__device__ __forceinline__ uint2 f4_to_h4(float4 v) {
    __half2 h01 = __floats2half2_rn(v.x, v.y);
    __half2 h23 = __floats2half2_rn(v.z, v.w);
    uint2 w;
    w.x = *reinterpret_cast<uint32_t*>(&h01);
    w.y = *reinterpret_cast<uint32_t*>(&h23);
    return w;
}

// ---------------- tiny kernels ----------------
__global__ void combine_rowsum(const float* __restrict__ cmb, float* __restrict__ S) {
    int row = blockIdx.x * (blockDim.x >> 5) + (threadIdx.x >> 5);
    int lane = threadIdx.x & 31;
    const float4* p = reinterpret_cast<const float4*>(cmb + (size_t)row * 2048);
    float s = 0.f;
    #pragma unroll 4
    for (int j = lane; j < 512; j += 32) {
        float4 v = p[j];
        s += (v.x + v.y) + (v.z + v.w);
    }
    #pragma unroll
    for (int o = 16; o; o >>= 1) s += __shfl_xor_sync(0xffffffffu, s, o);
    if (lane == 0) S[row] = s;
}

// elementwise fp32 -> fp16 (4 per thread)
__global__ void to_half(const float* __restrict__ in, __half* __restrict__ out) {
    size_t i = ((size_t)blockIdx.x * blockDim.x + threadIdx.x) * 4;
    float4 v = *reinterpret_cast<const float4*>(in + i);
    *reinterpret_cast<uint2*>(out + i) = f4_to_h4(v);
}

// Wh[o, e*512 + j] = half(weight_flat[e*4194304 + o*512 + j])
__global__ void permute_w_h(const float* __restrict__ in, __half* __restrict__ out) {
    size_t idx = (size_t)blockIdx.x * blockDim.x + threadIdx.x;  // 4,194,304 threads
    int j4 = (int)(idx & 127);
    int o  = (int)((idx >> 7) & 8191);
    int e  = (int)(idx >> 20);
    float4 v = *reinterpret_cast<const float4*>(in + (size_t)e * 4194304 + (size_t)o * 512 + j4 * 4);
    *reinterpret_cast<uint2*>(out + (size_t)o * 2048 + e * 512 + j4 * 4) = f4_to_h4(v);
}

__device__ __forceinline__ void cp16(uint32_t dst, const void* src) {
    asm volatile("cp.async.cg.shared.global [%0], [%1], 16;" :: "r"(dst), "l"(src));
}

// ---------------- fp16 GEMM (stages 1 & 2), all-half, cp.async double-buffer ------------
// C[M,N](half) = A @ B, tiles 128x128xBK32, 8 warps (4M x 2N), warp tile 32x64.
//   A_MK=true : A half (m,k) k-contig -> smem (m,k) pitch 20 u32, direct LDS frags
//   A_MK=false: A half (k,m) m-contig -> smem (k,m) pitch 68 u32, ldmatrix.trans
//   B        : B half (k,n) n-contig -> smem (k,n) pitch 68 u32, ldmatrix.trans
#define SBK 32
#define APK 20      // u32 pitch, A (m,k) layout (40 halves)
#define AKM 68      // u32 pitch, A (k,m) layout (136 halves)
#define BKN 68      // u32 pitch, B (k,n) layout

template <bool A_MK>
__global__ void __launch_bounds__(256, 2) gemm_h16(
    const __half* __restrict__ Ag, const __half* __restrict__ Bg, __half* __restrict__ Cg,
    int K, long long lda, long long ldb, long long ldc,
    long long aOut, long long aIn, long long bOut, long long bIn,
    long long cOut, long long cIn, int innerCount)
{
    constexpr int A_WORDS = A_MK ? 128 * APK : SBK * AKM;   // 2560 / 2176
    constexpr int B_WORDS = SBK * BKN;                       // 2176
    __shared__ uint32_t sA[2 * A_WORDS];
    __shared__ uint32_t sB[2 * B_WORDS];

    uint32_t sAb, sBb;
    asm("{ .reg .u64 t; cvta.to.shared.u64 t, %1; cvt.u32.u64 %0, t; }" : "=r"(sAb) : "l"(sA));
    asm("{ .reg .u64 t; cvta.to.shared.u64 t, %1; cvt.u32.u64 %0, t; }" : "=r"(sBb) : "l"(sB));

    const int z  = blockIdx.z;
    const int zo = z / innerCount;
    const int zi = z - zo * innerCount;
    const __half* A = Ag + (long long)zo * aOut + (long long)zi * aIn;
    const __half* B = Bg + (long long)zo * bOut + (long long)zi * bIn;

    const int m0g = blockIdx.y * 128;
    const int n0g = blockIdx.x * 128;
    const int tid  = threadIdx.x;
    const int warp = tid >> 5;
    const int lane = tid & 31;
    const int wm = warp & 3;        // 4 warps along M, 32 rows each
    const int wn = warp >> 2;       // 2 warps along N, 64 cols each
    const int g  = lane >> 2;
    const int tg = lane & 3;

    float acc[2][8][4];
    #pragma unroll
    for (int mi = 0; mi < 2; mi++)
        #pragma unroll
        for (int ni = 0; ni < 8; ni++)
            #pragma unroll
            for (int q = 0; q < 4; q++) acc[mi][ni][q] = 0.f;

    const int KTl = K / SBK;

    auto load_tile = [&](int buf, int kt) {
        const int k0g = kt * SBK;
        if constexpr (A_MK) {          // (m,k): 128 rows x 4 chunks of 8 halves
            const uint32_t base = sAb + (uint32_t)buf * (A_WORDS * 4);
            #pragma unroll
            for (int j = 0; j < 2; j++) {
                int idx = tid + j * 256;
                int m = idx >> 2, c = idx & 3;
                cp16(base + (uint32_t)(m * (APK * 4) + c * 16),
                     A + (long long)(m0g + m) * lda + k0g + c * 8);
            }
        } else {                       // (k,m): 32 rows x 16 chunks
            const uint32_t base = sAb + (uint32_t)buf * (A_WORDS * 4);
            #pragma unroll
            for (int j = 0; j < 2; j++) {
                int idx = tid + j * 256;
                int k = idx >> 4, c = idx & 15;
                cp16(base + (uint32_t)(k * (AKM * 4) + c * 16),
                     A + (long long)(k0g + k) * lda + m0g + c * 8);
            }
        }
        {                              // B (k,n): 32 rows x 16 chunks
            const uint32_t base = sBb + (uint32_t)buf * (B_WORDS * 4);
            #pragma unroll
            for (int j = 0; j < 2; j++) {
                int idx = tid + j * 256;
                int k = idx >> 4, c = idx & 15;
                cp16(base + (uint32_t)(k * (BKN * 4) + c * 16),
                     B + (long long)(k0g + k) * ldb + n0g + c * 8);
            }
        }
        asm volatile("cp.async.commit_group;" ::: "memory");
    };

    load_tile(0, 0);

    for (int kt = 0; kt < KTl; kt++) {
        asm volatile("cp.async.wait_group 0;" ::: "memory");
        __syncthreads();

        if (kt + 1 < KTl) load_tile((kt + 1) & 1, kt + 1);

        const int bufA = (kt & 1) * A_WORDS;
        const uint32_t sAbuf = sAb + (uint32_t)((kt & 1) * (A_WORDS * 4));
        const uint32_t sBbuf = sBb + (uint32_t)((kt & 1) * (B_WORDS * 4));

        #pragma unroll
        for (int ks = 0; ks < 2; ks++) {       // 2 x k16
            uint32_t af[2][4], bf[8][2];
            #pragma unroll
            for (int mi = 0; mi < 2; mi++) {
                const int rb = wm * 32 + mi * 16;
                if constexpr (A_MK) {
                    af[mi][0] = sA[bufA + (rb + g)     * APK + ks * 8 + tg];
                    af[mi][1] = sA[bufA + (rb + 8 + g) * APK + ks * 8 + tg];
                    af[mi][2] = sA[bufA + (rb + g)     * APK + ks * 8 + 4 + tg];
                    af[mi][3] = sA[bufA + (rb + 8 + g) * APK + ks * 8 + 4 + tg];
                } else {
                    const uint32_t row = (uint32_t)(ks * 16 + (lane & 7) + (((lane >> 4) & 1) << 3));
                    const uint32_t col = (uint32_t)(rb + (((lane >> 3) & 1) << 3));
                    const uint32_t addr = sAbuf + row * (AKM * 4) + col * 2;
                    asm volatile("ldmatrix.sync.aligned.m8n8.x4.trans.shared.b16 {%0,%1,%2,%3}, [%4];"
                                 : "=r"(af[mi][0]), "=r"(af[mi][1]), "=r"(af[mi][2]), "=r"(af[mi][3])
                                 : "r"(addr));
                }
            }
            #pragma unroll
            for (int np = 0; np < 4; np++) {   // each x4 covers ni = 2np, 2np+1
                const uint32_t row = (uint32_t)(ks * 16 + (lane & 7) + (((lane >> 3) & 1) << 3));
                const uint32_t col = (uint32_t)(wn * 64 + np * 16 + (((lane >> 4) & 1) << 3));
                const uint32_t addr = sBbuf + row * (BKN * 4) + col * 2;
                asm volatile("ldmatrix.sync.aligned.m8n8.x4.trans.shared.b16 {%0,%1,%2,%3}, [%4];"
                             : "=r"(bf[2 * np][0]), "=r"(bf[2 * np][1]),
                               "=r"(bf[2 * np + 1][0]), "=r"(bf[2 * np + 1][1])
                             : "r"(addr));
            }
            #pragma unroll
            for (int mi = 0; mi < 2; mi++)
                #pragma unroll
                for (int ni = 0; ni < 8; ni++)
                    asm volatile(
                        "mma.sync.aligned.m16n8k16.row.col.f32.f16.f16.f32 "
                        "{%0,%1,%2,%3}, {%4,%5,%6,%7}, {%8,%9}, {%0,%1,%2,%3};\n"
                        : "+f"(acc[mi][ni][0]), "+f"(acc[mi][ni][1]),
                          "+f"(acc[mi][ni][2]), "+f"(acc[mi][ni][3])
                        : "r"(af[mi][0]), "r"(af[mi][1]), "r"(af[mi][2]), "r"(af[mi][3]),
                          "r"(bf[ni][0]), "r"(bf[ni][1]));
        }
    }

    __half* C = Cg + (long long)zo * cOut + (long long)zi * cIn;
    #pragma unroll
    for (int mi = 0; mi < 2; mi++) {
        const int r0 = m0g + wm * 32 + mi * 16 + g;
        #pragma unroll
        for (int ni = 0; ni < 8; ni++) {
            const int c0 = n0g + wn * 64 + ni * 8 + tg * 2;
            __half2 h0 = __floats2half2_rn(acc[mi][ni][0], acc[mi][ni][1]);
            __half2 h1 = __floats2half2_rn(acc[mi][ni][2], acc[mi][ni][3]);
            *reinterpret_cast<__half2*>(&C[(long long)r0 * ldc + c0]) = h0;
            *reinterpret_cast<__half2*>(&C[(long long)(r0 + 8) * ldc + c0]) = h1;
        }
    }
}

// ---------------- big GEMM (fp16 + LDSM): out = Zh @ Wh^T + bias (x) S ----------------
#define TM 128
#define TN 256
#define HBK 64
#define NST 4
#define HKT 32                              // 2048 / 64
#define HPITCH 36                           // u32 per row (72 halves; 144B pitch)
#define A_WORDS3 (TM * HPITCH)              // 4608 u32
#define B_WORDS3 (TN * HPITCH)              // 9216 u32
#define STG_WORDS (A_WORDS3 + B_WORDS3)     // 13824 u32
#define BIG_SMEM (NST * STG_WORDS * 4)      // 221184 bytes

__global__ void __launch_bounds__(256) big_gemm_h(
    const __half* __restrict__ Z, const __half* __restrict__ W,
    const float* __restrict__ bias, const float* __restrict__ S,
    float* __restrict__ out)
{
    extern __shared__ uint32_t smem[];
    uint32_t sbase;
    asm("{ .reg .u64 t; cvta.to.shared.u64 t, %1; cvt.u32.u64 %0, t; }"
        : "=r"(sbase) : "l"(smem));

    const int tid  = threadIdx.x;
    const int warp = tid >> 5;
    const int lane = tid & 31;
    const int wm = warp & 1;        // 2 warps along M (64 rows each)
    const int wn = warp >> 1;       // 4 warps along N (64 cols each)
    const int g  = lane >> 2;
    const int tg = lane & 3;

    const int m0 = blockIdx.x * TM;
    const int n0 = blockIdx.y * TN;
    const __half* Ab = Z + (size_t)m0 * 2048;
    const __half* Bb = W + (size_t)n0 * 2048;

    const uint32_t aRow = (uint32_t)((lane & 7) + (lane & 8));
    const uint32_t aCol = (uint32_t)((lane >> 4) << 4);
    const uint32_t bRow = (uint32_t)((lane & 7) + ((lane >> 4) << 3));
    const uint32_t bCol = (uint32_t)((lane & 8) << 1);

    float acc[4][8][4];
    #pragma unroll
    for (int mi = 0; mi < 4; mi++)
        #pragma unroll
        for (int ni = 0; ni < 8; ni++)
            #pragma unroll
            for (int q = 0; q < 4; q++) acc[mi][ni][q] = 0.f;

    auto load_tile = [&](int stg, int kt) {
        const uint32_t sA = sbase + (uint32_t)stg * (STG_WORDS * 4);
        const uint32_t sB = sA + A_WORDS3 * 4;
        const __half* As = Ab + kt * HBK;
        const __half* Bs = Bb + kt * HBK;
        #pragma unroll
        for (int j = 0; j < 4; j++) {
            int idx = tid + j * 256;
            int r = idx >> 3, c = idx & 7;
            cp16(sA + (uint32_t)(r * (HPITCH * 4) + c * 16), As + (size_t)r * 2048 + c * 8);
        }
        #pragma unroll
        for (int j = 0; j < 8; j++) {
            int idx = tid + j * 256;
            int r = idx >> 3, c = idx & 7;
            cp16(sB + (uint32_t)(r * (HPITCH * 4) + c * 16), Bs + (size_t)r * 2048 + c * 8);
        }
    };

    #pragma unroll
    for (int s = 0; s < NST - 1; s++) {
        load_tile(s, s);
        asm volatile("cp.async.commit_group;" ::: "memory");
    }

    for (int kt = 0; kt < HKT; kt++) {
        asm volatile("cp.async.wait_group 2;" ::: "memory");
        __syncthreads();

        if (kt + NST - 1 < HKT) load_tile((kt + NST - 1) & (NST - 1), kt + NST - 1);
        asm volatile("cp.async.commit_group;" ::: "memory");

        const uint32_t sAb = sbase + (uint32_t)((kt & (NST - 1)) * (STG_WORDS * 4));
        const uint32_t sBb = sAb + A_WORDS3 * 4;

        #pragma unroll
        for (int ks = 0; ks < 4; ks++) {
            const uint32_t kbyte = (uint32_t)(ks * 32);
            uint32_t af[4][4], bf[8][2];
            #pragma unroll
            for (int mi = 0; mi < 4; mi++) {
                const uint32_t addr = sAb + (uint32_t)(wm * 64 + mi * 16 + aRow) * (HPITCH * 4)
                                    + kbyte + aCol;
                asm volatile("ldmatrix.sync.aligned.m8n8.x4.shared.b16 {%0,%1,%2,%3}, [%4];"
                             : "=r"(af[mi][0]), "=r"(af[mi][1]), "=r"(af[mi][2]), "=r"(af[mi][3])
                             : "r"(addr));
            }
            #pragma unroll
            for (int np = 0; np < 4; np++) {
                const uint32_t addr = sBb + (uint32_t)(wn * 64 + np * 16 + bRow) * (HPITCH * 4)
                                    + kbyte + bCol;
                asm volatile("ldmatrix.sync.aligned.m8n8.x4.shared.b16 {%0,%1,%2,%3}, [%4];"
                             : "=r"(bf[2 * np][0]), "=r"(bf[2 * np][1]),
                               "=r"(bf[2 * np + 1][0]), "=r"(bf[2 * np + 1][1])
                             : "r"(addr));
            }
            #pragma unroll
            for (int mi = 0; mi < 4; mi++)
                #pragma unroll
                for (int ni = 0; ni < 8; ni++)
                    asm volatile(
                        "mma.sync.aligned.m16n8k16.row.col.f32.f16.f16.f32 "
                        "{%0,%1,%2,%3}, {%4,%5,%6,%7}, {%8,%9}, {%0,%1,%2,%3};\n"
                        : "+f"(acc[mi][ni][0]), "+f"(acc[mi][ni][1]),
                          "+f"(acc[mi][ni][2]), "+f"(acc[mi][ni][3])
                        : "r"(af[mi][0]), "r"(af[mi][1]), "r"(af[mi][2]), "r"(af[mi][3]),
                          "r"(bf[ni][0]), "r"(bf[ni][1]));
        }
    }

    #pragma unroll
    for (int mi = 0; mi < 4; mi++) {
        const int r0 = m0 + wm * 64 + mi * 16 + g;
        const float s0 = S[r0], s1 = S[r0 + 8];
        #pragma unroll
        for (int ni = 0; ni < 8; ni++) {
            const int c0 = n0 + wn * 64 + ni * 8 + tg * 2;
            const float b0 = bias[c0], b1 = bias[c0 + 1];
            float2 v0 = make_float2(acc[mi][ni][0] + b0 * s0, acc[mi][ni][1] + b1 * s0);
            float2 v1 = make_float2(acc[mi][ni][2] + b0 * s1, acc[mi][ni][3] + b1 * s1);
            *reinterpret_cast<float2*>(&out[(size_t)r0 * 8192 + c0]) = v0;
            *reinterpret_cast<float2*>(&out[(size_t)(r0 + 8) * 8192 + c0]) = v1;
        }
    }
}

// ---------------- launch ----------------
extern "C" void kernel_launch(void* const* d_in, const int* in_sizes, int n_in,
                              void* d_out, int out_size)
{
    const float* x      = (const float*)d_in[0];  // (4,1024,2048)
    const float* cmb    = (const float*)d_in[1];  // (4,1024,4,512)
    const float* mask   = (const float*)d_in[2];  // (4,1024,4,512)
    const float* weight = (const float*)d_in[3];  // (8192,2048)
    const float* bias   = (const float*)d_in[4];  // (8192,)
    float* out = (float*)d_out;                   // (4,1024,8192)

    float *S;
    __half *xh, *mh, *ch, *Xd, *Zh, *Wh;
    cudaGetSymbolAddress((void**)&xh, g_xh);
    cudaGetSymbolAddress((void**)&mh, g_mh);
    cudaGetSymbolAddress((void**)&ch, g_ch);
    cudaGetSymbolAddress((void**)&Xd, g_Xd);
    cudaGetSymbolAddress((void**)&Zh, g_Zh);
    cudaGetSymbolAddress((void**)&Wh, g_Wh);
    cudaGetSymbolAddress((void**)&S,  g_S);

    combine_rowsum<<<512, 256>>>(cmb, S);
    to_half<<<8192, 256>>>(x, xh);      // 8,388,608 elems
    to_half<<<8192, 256>>>(mask, mh);
    to_half<<<8192, 256>>>(cmb, ch);
    permute_w_h<<<16384, 256>>>(weight, Wh);

    // Stage 1: Xd[b,e](512x512,half) = mask^T @ x-slice   (A half (k,m), B half (k,n))
    {
        dim3 grid(512 / 128, 512 / 128, 16);
        gemm_h16<false><<<grid, 256>>>(
            mh, xh, Xd, 1024, 2048, 2048, 512,
            2097152LL, 512LL, 2097152LL, 512LL,
            1048576LL, 262144LL, 4);
    }
    // Stage 2: Zh[b,:,e*512:](1024x512) = cmb @ Xd[b,e]   (A half (m,k), B half (k,n))
    {
        dim3 grid(512 / 128, 1024 / 128, 16);
        gemm_h16<true><<<grid, 256>>>(
            ch, Xd, Zh, 512, 2048, 512, 2048,
            2097152LL, 512LL, 1048576LL, 262144LL,
            2097152LL, 512LL, 4);
    }
    // Stage 3: out = Zh(4096x2048) @ Wh^T(2048x8192) + bias (x) S   (fp16 MMA + LDSM)
    {
        cudaFuncSetAttribute(big_gemm_h, cudaFuncAttributeMaxDynamicSharedMemorySize, BIG_SMEM);
        dim3 grid(4096 / TM, 8192 / TN, 1);
        big_gemm_h<<<grid, 256, BIG_SMEM>>>(Zh, Wh, bias, S, out);
    }
}

// round 11
// speedup vs baseline: 1.4668x; 1.4668x over previous
#include <cuda_runtime.h>
#include <cuda_fp16.h>
#include <cstdint>
#include <cstddef>

// Problem: B=4, T=1024, E=4, C=512, i=512, IN=2048, OUT=8192
//   w[e,o,j] = weight_flat[e*4194304 + o*512 + j]   (torch-style reshape)
//   Xd[b,e] = mask[b,:,e,:]^T @ x[b,:,e*512:]        (fp16 MMA, half out)
//   Zh[b,:,e*512:] = cmb[b,:,e,:] @ Xd[b,e]          (fp16 MMA, half out)
//   out[b] = Zh[b] @ Wh^T + bias (x) rowsum(cmb)     (fp16 MMA, M=4096,N=8192,K=2048)

// ---------------- scratch (allocation-free rule) ----------------
static __device__ __half g_Xd[4ull * 4 * 512 * 512];   // 8 MB (half)
static __device__ __half g_Zh[4096ull * 2048];         // 16 MB
static __device__ __half g_Wh[8192ull * 2048];         // 32 MB (permuted half weight)
static __device__ float  g_S [4 * 1024];

// ---------------- tiny kernels ----------------
__global__ void combine_rowsum(const float* __restrict__ cmb, float* __restrict__ S) {
    int row = blockIdx.x * (blockDim.x >> 5) + (threadIdx.x >> 5);
    int lane = threadIdx.x & 31;
    const float4* p = reinterpret_cast<const float4*>(cmb + (size_t)row * 2048);
    float s = 0.f;
    #pragma unroll 4
    for (int j = lane; j < 512; j += 32) {
        float4 v = p[j];
        s += (v.x + v.y) + (v.z + v.w);
    }
    #pragma unroll
    for (int o = 16; o; o >>= 1) s += __shfl_xor_sync(0xffffffffu, s, o);
    if (lane == 0) S[row] = s;
}

__device__ __forceinline__ uint2 f4_to_h4(float4 v) {
    __half2 h01 = __floats2half2_rn(v.x, v.y);
    __half2 h23 = __floats2half2_rn(v.z, v.w);
    uint2 w;
    w.x = *reinterpret_cast<uint32_t*>(&h01);
    w.y = *reinterpret_cast<uint32_t*>(&h23);
    return w;
}

// Wh[o, e*512 + j] = half(weight_flat[e*4194304 + o*512 + j])
__global__ void permute_w_h(const float* __restrict__ in, __half* __restrict__ out) {
    size_t idx = (size_t)blockIdx.x * blockDim.x + threadIdx.x;  // 4,194,304 threads
    int j4 = (int)(idx & 127);
    int o  = (int)((idx >> 7) & 8191);
    int e  = (int)(idx >> 20);
    float4 v = *reinterpret_cast<const float4*>(in + (size_t)e * 4194304 + (size_t)o * 512 + j4 * 4);
    *reinterpret_cast<uint2*>(out + (size_t)o * 2048 + e * 512 + j4 * 4) = f4_to_h4(v);
}

// ---------------- fp16 SIMT GEMM (stages 1 & 2) — R9 proven version ----------------
#define SBK 32
#define APK 20      // u32 pitch, A (m,k-pair) layout
#define AKM 68      // u32 pitch, A (k,m) layout (136 halves)
#define BKN 68      // u32 pitch, B (k,n) layout

template <bool A_MK, bool B_HALF>
__global__ void __launch_bounds__(256, 2) gemm_h16(
    const void* __restrict__ Ag, const void* __restrict__ Bg, __half* __restrict__ Cg,
    int K, long long lda, long long ldb, long long ldc,
    long long aOut, long long aIn, long long bOut, long long bIn,
    long long cOut, long long cIn, int innerCount)
{
    constexpr int A_WORDS = A_MK ? 128 * APK : SBK * AKM;
    __shared__ uint32_t sA[A_WORDS];
    __shared__ uint32_t sB[SBK * BKN];

    uint32_t sAb, sBb;
    asm("{ .reg .u64 t; cvta.to.shared.u64 t, %1; cvt.u32.u64 %0, t; }" : "=r"(sAb) : "l"(sA));
    asm("{ .reg .u64 t; cvta.to.shared.u64 t, %1; cvt.u32.u64 %0, t; }" : "=r"(sBb) : "l"(sB));

    const int z  = blockIdx.z;
    const int zo = z / innerCount;
    const int zi = z - zo * innerCount;

    const int m0g = blockIdx.y * 128;
    const int n0g = blockIdx.x * 128;
    const int tid  = threadIdx.x;
    const int warp = tid >> 5;
    const int lane = tid & 31;
    const int wm = warp & 3;        // 4 warps along M, 32 rows each
    const int wn = warp >> 2;       // 2 warps along N, 64 cols each
    const int g  = lane >> 2;
    const int tg = lane & 3;

    float acc[2][8][4];
    #pragma unroll
    for (int mi = 0; mi < 2; mi++)
        #pragma unroll
        for (int ni = 0; ni < 8; ni++)
            #pragma unroll
            for (int q = 0; q < 4; q++) acc[mi][ni][q] = 0.f;

    for (int k0g = 0; k0g < K; k0g += SBK) {
        // ---- A -> smem ----
        if constexpr (A_MK) {          // fp32 (m,k) k-contig: 128x32 = 1024 float4
            const float* A = (const float*)Ag + (long long)zo * aOut + (long long)zi * aIn;
            #pragma unroll
            for (int j = 0; j < 4; j++) {
                int idx = tid + j * 256;
                int m = idx >> 3, k4 = idx & 7;
                float4 v = *reinterpret_cast<const float4*>(&A[(long long)(m0g + m) * lda + k0g + k4 * 4]);
                *reinterpret_cast<uint2*>(&sA[m * APK + k4 * 2]) = f4_to_h4(v);
            }
        } else {                       // fp32 (k,m) m-contig: 32x128 = 1024 float4
            const float* A = (const float*)Ag + (long long)zo * aOut + (long long)zi * aIn;
            #pragma unroll
            for (int j = 0; j < 4; j++) {
                int idx = tid + j * 256;
                int k = idx >> 5, m4 = idx & 31;
                float4 v = *reinterpret_cast<const float4*>(&A[(long long)(k0g + k) * lda + m0g + m4 * 4]);
                *reinterpret_cast<uint2*>(&sA[k * AKM + m4 * 2]) = f4_to_h4(v);
            }
        }
        // ---- B -> smem ----
        if constexpr (B_HALF) {        // half (k,n) n-contig: 32x128 halves = 512 uint4
            const __half* B = (const __half*)Bg + (long long)zo * bOut + (long long)zi * bIn;
            #pragma unroll
            for (int j = 0; j < 2; j++) {
                int idx = tid + j * 256;
                int k = idx >> 4, n8 = idx & 15;
                uint4 v = *reinterpret_cast<const uint4*>(&B[(long long)(k0g + k) * ldb + n0g + n8 * 8]);
                *reinterpret_cast<uint4*>(&sB[k * BKN + n8 * 4]) = v;
            }
        } else {                       // fp32 (k,n) n-contig: 1024 float4
            const float* B = (const float*)Bg + (long long)zo * bOut + (long long)zi * bIn;
            #pragma unroll
            for (int j = 0; j < 4; j++) {
                int idx = tid + j * 256;
                int k = idx >> 5, n4 = idx & 31;
                float4 v = *reinterpret_cast<const float4*>(&B[(long long)(k0g + k) * ldb + n0g + n4 * 4]);
                *reinterpret_cast<uint2*>(&sB[k * BKN + n4 * 2]) = f4_to_h4(v);
            }
        }
        __syncthreads();

        #pragma unroll
        for (int ks = 0; ks < 2; ks++) {       // 2 x k16
            uint32_t af[2][4], bf[8][2];
            #pragma unroll
            for (int mi = 0; mi < 2; mi++) {
                const int rb = wm * 32 + mi * 16;
                if constexpr (A_MK) {
                    af[mi][0] = sA[(rb + g)     * APK + ks * 8 + tg];
                    af[mi][1] = sA[(rb + 8 + g) * APK + ks * 8 + tg];
                    af[mi][2] = sA[(rb + g)     * APK + ks * 8 + 4 + tg];
                    af[mi][3] = sA[(rb + 8 + g) * APK + ks * 8 + 4 + tg];
                } else {
                    const uint32_t row = (uint32_t)(ks * 16 + (lane & 7) + (((lane >> 4) & 1) << 3));
                    const uint32_t col = (uint32_t)(rb + (((lane >> 3) & 1) << 3));
                    const uint32_t addr = sAb + row * (AKM * 4) + col * 2;
                    asm volatile("ldmatrix.sync.aligned.m8n8.x4.trans.shared.b16 {%0,%1,%2,%3}, [%4];"
                                 : "=r"(af[mi][0]), "=r"(af[mi][1]), "=r"(af[mi][2]), "=r"(af[mi][3])
                                 : "r"(addr));
                }
            }
            #pragma unroll
            for (int np = 0; np < 4; np++) {   // each x4 covers ni = 2np, 2np+1
                const uint32_t row = (uint32_t)(ks * 16 + (lane & 7) + (((lane >> 3) & 1) << 3));
                const uint32_t col = (uint32_t)(wn * 64 + np * 16 + (((lane >> 4) & 1) << 3));
                const uint32_t addr = sBb + row * (BKN * 4) + col * 2;
                asm volatile("ldmatrix.sync.aligned.m8n8.x4.trans.shared.b16 {%0,%1,%2,%3}, [%4];"
                             : "=r"(bf[2 * np][0]), "=r"(bf[2 * np][1]),
                               "=r"(bf[2 * np + 1][0]), "=r"(bf[2 * np + 1][1])
                             : "r"(addr));
            }
            #pragma unroll
            for (int mi = 0; mi < 2; mi++)
                #pragma unroll
                for (int ni = 0; ni < 8; ni++)
                    asm volatile(
                        "mma.sync.aligned.m16n8k16.row.col.f32.f16.f16.f32 "
                        "{%0,%1,%2,%3}, {%4,%5,%6,%7}, {%8,%9}, {%0,%1,%2,%3};\n"
                        : "+f"(acc[mi][ni][0]), "+f"(acc[mi][ni][1]),
                          "+f"(acc[mi][ni][2]), "+f"(acc[mi][ni][3])
                        : "r"(af[mi][0]), "r"(af[mi][1]), "r"(af[mi][2]), "r"(af[mi][3]),
                          "r"(bf[ni][0]), "r"(bf[ni][1]));
        }
        __syncthreads();
    }

    __half* C = Cg + (long long)zo * cOut + (long long)zi * cIn;
    #pragma unroll
    for (int mi = 0; mi < 2; mi++) {
        const int r0 = m0g + wm * 32 + mi * 16 + g;
        #pragma unroll
        for (int ni = 0; ni < 8; ni++) {
            const int c0 = n0g + wn * 64 + ni * 8 + tg * 2;
            __half2 h0 = __floats2half2_rn(acc[mi][ni][0], acc[mi][ni][1]);
            __half2 h1 = __floats2half2_rn(acc[mi][ni][2], acc[mi][ni][3]);
            *reinterpret_cast<__half2*>(&C[(long long)r0 * ldc + c0]) = h0;
            *reinterpret_cast<__half2*>(&C[(long long)(r0 + 8) * ldc + c0]) = h1;
        }
    }
}

// ---------------- big GEMM (fp16 + LDSM, 512 threads): out = Zh @ Wh^T + bias (x) S ----
// CTA 128x256, BK=64 halves, 16 warps (4M x 4N), warp tile 32x64, 4-stage cp.async.
#define TM 128
#define TN 256
#define HBK 64
#define NST 4
#define HKT 32                              // 2048 / 64
#define HPITCH 36                           // u32 per row (72 halves; 144B pitch)
#define A_WORDS3 (TM * HPITCH)              // 4608 u32
#define B_WORDS3 (TN * HPITCH)              // 9216 u32
#define STG_WORDS (A_WORDS3 + B_WORDS3)     // 13824 u32
#define BIG_SMEM (NST * STG_WORDS * 4)      // 221184 bytes

__device__ __forceinline__ void cp16(uint32_t dst, const void* src) {
    asm volatile("cp.async.cg.shared.global [%0], [%1], 16;" :: "r"(dst), "l"(src));
}

__global__ void __launch_bounds__(512) big_gemm_h(
    const __half* __restrict__ Z, const __half* __restrict__ W,
    const float* __restrict__ bias, const float* __restrict__ S,
    float* __restrict__ out)
{
    extern __shared__ uint32_t smem[];
    uint32_t sbase;
    asm("{ .reg .u64 t; cvta.to.shared.u64 t, %1; cvt.u32.u64 %0, t; }"
        : "=r"(sbase) : "l"(smem));

    const int tid  = threadIdx.x;
    const int warp = tid >> 5;
    const int lane = tid & 31;
    const int wm = warp & 3;        // 4 warps along M (32 rows each)
    const int wn = warp >> 2;       // 4 warps along N (64 cols each)
    const int g  = lane >> 2;
    const int tg = lane & 3;

    const int m0 = blockIdx.x * TM;      // x fastest: wave = all M-tiles x few N-tiles
    const int n0 = blockIdx.y * TN;
    const __half* Ab = Z + (size_t)m0 * 2048;
    const __half* Bb = W + (size_t)n0 * 2048;

    // ldmatrix per-lane row/col components (byte offsets within tile) — validated R8/R9
    const uint32_t aRow = (uint32_t)((lane & 7) + (lane & 8));
    const uint32_t aCol = (uint32_t)((lane >> 4) << 4);
    const uint32_t bRow = (uint32_t)((lane & 7) + ((lane >> 4) << 3));
    const uint32_t bCol = (uint32_t)((lane & 8) << 1);

    float acc[2][8][4];
    #pragma unroll
    for (int mi = 0; mi < 2; mi++)
        #pragma unroll
        for (int ni = 0; ni < 8; ni++)
            #pragma unroll
            for (int q = 0; q < 4; q++) acc[mi][ni][q] = 0.f;

    auto load_tile = [&](int stg, int kt) {
        const uint32_t sA = sbase + (uint32_t)stg * (STG_WORDS * 4);
        const uint32_t sB = sA + A_WORDS3 * 4;
        const __half* As = Ab + kt * HBK;
        const __half* Bs = Bb + kt * HBK;
        #pragma unroll
        for (int j = 0; j < 2; j++) {            // A: 128 rows x 8 chunks = 1024
            int idx = tid + j * 512;
            int r = idx >> 3, c = idx & 7;
            cp16(sA + (uint32_t)(r * (HPITCH * 4) + c * 16), As + (size_t)r * 2048 + c * 8);
        }
        #pragma unroll
        for (int j = 0; j < 4; j++) {            // B: 256 rows x 8 chunks = 2048
            int idx = tid + j * 512;
            int r = idx >> 3, c = idx & 7;
            cp16(sB + (uint32_t)(r * (HPITCH * 4) + c * 16), Bs + (size_t)r * 2048 + c * 8);
        }
    };

    #pragma unroll
    for (int s = 0; s < NST - 1; s++) {
        load_tile(s, s);
        asm volatile("cp.async.commit_group;" ::: "memory");
    }

    for (int kt = 0; kt < HKT; kt++) {
        asm volatile("cp.async.wait_group 2;" ::: "memory");
        __syncthreads();

        if (kt + NST - 1 < HKT) load_tile((kt + NST - 1) & (NST - 1), kt + NST - 1);
        asm volatile("cp.async.commit_group;" ::: "memory");

        const uint32_t sAb = sbase + (uint32_t)((kt & (NST - 1)) * (STG_WORDS * 4));
        const uint32_t sBb = sAb + A_WORDS3 * 4;

        #pragma unroll
        for (int ks = 0; ks < 4; ks++) {
            const uint32_t kbyte = (uint32_t)(ks * 32);
            uint32_t af[2][4], bf[8][2];
            #pragma unroll
            for (int mi = 0; mi < 2; mi++) {
                const uint32_t addr = sAb + (uint32_t)(wm * 32 + mi * 16 + aRow) * (HPITCH * 4)
                                    + kbyte + aCol;
                asm volatile("ldmatrix.sync.aligned.m8n8.x4.shared.b16 {%0,%1,%2,%3}, [%4];"
                             : "=r"(af[mi][0]), "=r"(af[mi][1]), "=r"(af[mi][2]), "=r"(af[mi][3])
                             : "r"(addr));
            }
            #pragma unroll
            for (int np = 0; np < 4; np++) {
                const uint32_t addr = sBb + (uint32_t)(wn * 64 + np * 16 + bRow) * (HPITCH * 4)
                                    + kbyte + bCol;
                asm volatile("ldmatrix.sync.aligned.m8n8.x4.shared.b16 {%0,%1,%2,%3}, [%4];"
                             : "=r"(bf[2 * np][0]), "=r"(bf[2 * np][1]),
                               "=r"(bf[2 * np + 1][0]), "=r"(bf[2 * np + 1][1])
                             : "r"(addr));
            }
            #pragma unroll
            for (int mi = 0; mi < 2; mi++)
                #pragma unroll
                for (int ni = 0; ni < 8; ni++)
                    asm volatile(
                        "mma.sync.aligned.m16n8k16.row.col.f32.f16.f16.f32 "
                        "{%0,%1,%2,%3}, {%4,%5,%6,%7}, {%8,%9}, {%0,%1,%2,%3};\n"
                        : "+f"(acc[mi][ni][0]), "+f"(acc[mi][ni][1]),
                          "+f"(acc[mi][ni][2]), "+f"(acc[mi][ni][3])
                        : "r"(af[mi][0]), "r"(af[mi][1]), "r"(af[mi][2]), "r"(af[mi][3]),
                          "r"(bf[ni][0]), "r"(bf[ni][1]));
        }
    }

    // epilogue: out = acc + bias[n] * S[m]
    #pragma unroll
    for (int mi = 0; mi < 2; mi++) {
        const int r0 = m0 + wm * 32 + mi * 16 + g;
        const float s0 = S[r0], s1 = S[r0 + 8];
        #pragma unroll
        for (int ni = 0; ni < 8; ni++) {
            const int c0 = n0 + wn * 64 + ni * 8 + tg * 2;
            const float b0 = bias[c0], b1 = bias[c0 + 1];
            float2 v0 = make_float2(acc[mi][ni][0] + b0 * s0, acc[mi][ni][1] + b1 * s0);
            float2 v1 = make_float2(acc[mi][ni][2] + b0 * s1, acc[mi][ni][3] + b1 * s1);
            *reinterpret_cast<float2*>(&out[(size_t)r0 * 8192 + c0]) = v0;
            *reinterpret_cast<float2*>(&out[(size_t)(r0 + 8) * 8192 + c0]) = v1;
        }
    }
}

// ---------------- launch ----------------
extern "C" void kernel_launch(void* const* d_in, const int* in_sizes, int n_in,
                              void* d_out, int out_size)
{
    const float* x      = (const float*)d_in[0];  // (4,1024,2048)
    const float* cmb    = (const float*)d_in[1];  // (4,1024,4,512)
    const float* mask   = (const float*)d_in[2];  // (4,1024,4,512)
    const float* weight = (const float*)d_in[3];  // (8192,2048)
    const float* bias   = (const float*)d_in[4];  // (8192,)
    float* out = (float*)d_out;                   // (4,1024,8192)

    float *S;
    __half *Xd, *Zh, *Wh;
    cudaGetSymbolAddress((void**)&Xd, g_Xd);
    cudaGetSymbolAddress((void**)&Zh, g_Zh);
    cudaGetSymbolAddress((void**)&Wh, g_Wh);
    cudaGetSymbolAddress((void**)&S,  g_S);

    combine_rowsum<<<512, 256>>>(cmb, S);
    permute_w_h<<<16384, 256>>>(weight, Wh);

    // Stage 1: Xd[b,e](512x512,half) = mask^T @ x-slice   (A fp32 (k,m), B fp32 (k,n))
    {
        dim3 grid(512 / 128, 512 / 128, 16);
        gemm_h16<false, false><<<grid, 256>>>(
            mask, x, Xd, 1024, 2048, 2048, 512,
            2097152LL, 512LL, 2097152LL, 512LL,
            1048576LL, 262144LL, 4);
    }
    // Stage 2: Zh[b,:,e*512:](1024x512) = cmb @ Xd[b,e]   (A fp32 (m,k), B half (k,n))
    {
        dim3 grid(512 / 128, 1024 / 128, 16);
        gemm_h16<true, true><<<grid, 256>>>(
            cmb, Xd, Zh, 512, 2048, 512, 2048,
            2097152LL, 512LL, 1048576LL, 262144LL,
            2097152LL, 512LL, 4);
    }
    // Stage 3: out = Zh(4096x2048) @ Wh^T(2048x8192) + bias (x) S   (fp16 MMA + LDSM, 512t)
    {
        cudaFuncSetAttribute(big_gemm_h, cudaFuncAttributeMaxDynamicSharedMemorySize, BIG_SMEM);
        dim3 grid(4096 / TM, 8192 / TN, 1);
        big_gemm_h<<<grid, 512, BIG_SMEM>>>(Zh, Wh, bias, S, out);
    }
}

// round 13
// speedup vs baseline: 1.5380x; 1.0485x over previous
#include <cuda_runtime.h>
#include <cuda_fp16.h>
#include <cstdint>
#include <cstddef>

// Problem: B=4, T=1024, E=4, C=512, i=512, IN=2048, OUT=8192
//   w[e,o,j] = weight_flat[e*4194304 + o*512 + j]   (torch-style reshape)
//   Xd[b,e] = mask[b,:,e,:]^T @ x[b,:,e*512:]        (fp16 MMA, half out)
//   Zh[b,:,e*512:] = cmb[b,:,e,:] @ Xd[b,e]          (fp16 MMA, half out)
//   out[b] = Zh[b] @ Wh^T + bias (x) rowsum(cmb)     (fp16 MMA, M=4096,N=8192,K=2048)

// ---------------- scratch (allocation-free rule) ----------------
static __device__ __half g_xh[4ull * 1024 * 2048];     // 8,388,608 halves
static __device__ __half g_mh[4ull * 1024 * 4 * 512];  // 8,388,608 halves
static __device__ __half g_ch[4ull * 1024 * 4 * 512];  // 8,388,608 halves
static __device__ __half g_Xd[4ull * 4 * 512 * 512];   // 4,194,304 halves
static __device__ __half g_Zh[4096ull * 2048];         // 8,388,608 halves
static __device__ __half g_Wh[8192ull * 2048];         // permuted half weight
static __device__ float  g_S [4 * 1024];

__device__ __forceinline__ uint2 f4_to_h4(float4 v) {
    __half2 h01 = __floats2half2_rn(v.x, v.y);
    __half2 h23 = __floats2half2_rn(v.z, v.w);
    uint2 w;
    w.x = *reinterpret_cast<uint32_t*>(&h01);
    w.y = *reinterpret_cast<uint32_t*>(&h23);
    return w;
}

// ---------------- fused prep: cmb->half (+rowsum S), mask->half, x->half ----------------
// blocks [0,512):      cmb rows (8 rows/block, 1 warp/row) convert + rowsum (4096 rows x 2048)
// blocks [512,8704):   mask, 1024 elems/block (8,388,608 total)
// blocks [8704,16896): x,    1024 elems/block (8,388,608 total)
__global__ void prep_inputs(const float* __restrict__ cmb, const float* __restrict__ mask,
                            const float* __restrict__ x,
                            __half* __restrict__ ch, __half* __restrict__ mh,
                            __half* __restrict__ xh, float* __restrict__ S)
{
    const int blk = blockIdx.x;
    if (blk < 512) {
        const int wid = threadIdx.x >> 5, lane = threadIdx.x & 31;
        const int row = blk * 8 + wid;
        const float4* src = reinterpret_cast<const float4*>(cmb + (size_t)row * 2048);
        uint2* dst = reinterpret_cast<uint2*>(ch + (size_t)row * 2048);
        float s = 0.f;
        #pragma unroll
        for (int it = 0; it < 16; it++) {
            int j = lane + it * 32;
            float4 v = src[j];
            s += (v.x + v.y) + (v.z + v.w);
            dst[j] = f4_to_h4(v);
        }
        #pragma unroll
        for (int o = 16; o; o >>= 1) s += __shfl_xor_sync(0xffffffffu, s, o);
        if (lane == 0) S[row] = s;
    } else if (blk < 8704) {
        size_t i = ((size_t)(blk - 512) * 256 + threadIdx.x) * 4;
        float4 v = *reinterpret_cast<const float4*>(mask + i);
        *reinterpret_cast<uint2*>(mh + i) = f4_to_h4(v);
    } else {
        size_t i = ((size_t)(blk - 8704) * 256 + threadIdx.x) * 4;
        float4 v = *reinterpret_cast<const float4*>(x + i);
        *reinterpret_cast<uint2*>(xh + i) = f4_to_h4(v);
    }
}

// Wh[o, e*512 + j] = half(weight_flat[e*4194304 + o*512 + j])
__global__ void permute_w_h(const float* __restrict__ in, __half* __restrict__ out) {
    size_t idx = (size_t)blockIdx.x * blockDim.x + threadIdx.x;  // 4,194,304 threads
    int j4 = (int)(idx & 127);
    int o  = (int)((idx >> 7) & 8191);
    int e  = (int)(idx >> 20);
    float4 v = *reinterpret_cast<const float4*>(in + (size_t)e * 4194304 + (size_t)o * 512 + j4 * 4);
    *reinterpret_cast<uint2*>(out + (size_t)o * 2048 + e * 512 + j4 * 4) = f4_to_h4(v);
}

__device__ __forceinline__ void cp16(uint32_t dst, const void* src) {
    asm volatile("cp.async.cg.shared.global [%0], [%1], 16;" :: "r"(dst), "l"(src));
}

// ---------------- fp16 GEMM (stages 1 & 2): all-half, 3-stage cp.async pipeline --------
// C[M,N](half) = A @ B, tiles 128x128xBK32, 8 warps (4M x 2N), warp tile 32x64.
//   A_MK=true : A half (m,k) k-contig -> smem (m,k) pitch 20 u32, direct LDS frags
//   A_MK=false: A half (k,m) m-contig -> smem (k,m) pitch 68 u32, ldmatrix.trans
//   B         : B half (k,n) n-contig -> smem (k,n) pitch 68 u32, ldmatrix.trans
#define SBK 32
#define APK 20
#define AKM 68
#define BKN 68
#define SNST 3

template <bool A_MK>
__global__ void __launch_bounds__(256, 2) gemm_h16(
    const __half* __restrict__ Ag, const __half* __restrict__ Bg, __half* __restrict__ Cg,
    int K, long long lda, long long ldb, long long ldc,
    long long aOut, long long aIn, long long bOut, long long bIn,
    long long cOut, long long cIn, int innerCount)
{
    constexpr int A_WORDS = A_MK ? 128 * APK : SBK * AKM;   // 2560 / 2176
    constexpr int B_WORDS = SBK * BKN;                      // 2176
    constexpr int STGW = A_WORDS + B_WORDS;
    extern __shared__ uint32_t smem[];
    uint32_t sbase;
    asm("{ .reg .u64 t; cvta.to.shared.u64 t, %1; cvt.u32.u64 %0, t; }" : "=r"(sbase) : "l"(smem));

    const int z  = blockIdx.z;
    const int zo = z / innerCount;
    const int zi = z - zo * innerCount;
    const __half* A = Ag + (long long)zo * aOut + (long long)zi * aIn;
    const __half* B = Bg + (long long)zo * bOut + (long long)zi * bIn;

    const int m0g = blockIdx.y * 128;
    const int n0g = blockIdx.x * 128;
    const int tid  = threadIdx.x;
    const int warp = tid >> 5;
    const int lane = tid & 31;
    const int wm = warp & 3;        // 4 warps along M, 32 rows each
    const int wn = warp >> 2;       // 2 warps along N, 64 cols each
    const int g  = lane >> 2;
    const int tg = lane & 3;

    float acc[2][8][4];
    #pragma unroll
    for (int mi = 0; mi < 2; mi++)
        #pragma unroll
        for (int ni = 0; ni < 8; ni++)
            #pragma unroll
            for (int q = 0; q < 4; q++) acc[mi][ni][q] = 0.f;

    const int KTl = K / SBK;

    auto load_tile = [&](int buf, int kt) {
        const int k0g = kt * SBK;
        const uint32_t aBase = sbase + (uint32_t)(buf * STGW * 4);
        const uint32_t bBase = aBase + A_WORDS * 4;
        if constexpr (A_MK) {          // (m,k): 128 rows x 4 chunks (16B) = 512
            #pragma unroll
            for (int j = 0; j < 2; j++) {
                int idx = tid + j * 256;
                int m = idx >> 2, c = idx & 3;
                cp16(aBase + (uint32_t)(m * (APK * 4) + c * 16),
                     A + (long long)(m0g + m) * lda + k0g + c * 8);
            }
        } else {                       // (k,m): 32 rows x 16 chunks = 512
            #pragma unroll
            for (int j = 0; j < 2; j++) {
                int idx = tid + j * 256;
                int k = idx >> 4, c = idx & 15;
                cp16(aBase + (uint32_t)(k * (AKM * 4) + c * 16),
                     A + (long long)(k0g + k) * lda + m0g + c * 8);
            }
        }
        #pragma unroll
        for (int j = 0; j < 2; j++) {  // B (k,n): 32 rows x 16 chunks = 512
            int idx = tid + j * 256;
            int k = idx >> 4, c = idx & 15;
            cp16(bBase + (uint32_t)(k * (BKN * 4) + c * 16),
                 B + (long long)(k0g + k) * ldb + n0g + c * 8);
        }
        asm volatile("cp.async.commit_group;" ::: "memory");
    };

    // prologue: tiles 0,1 -> bufs 0,1
    load_tile(0, 0);
    load_tile(1, 1);

    for (int kt = 0; kt < KTl; kt++) {
        asm volatile("cp.async.wait_group 1;" ::: "memory");   // tile kt landed; kt+1 may fly
        __syncthreads();

        if (kt + 2 < KTl) load_tile((kt + 2) % SNST, kt + 2);
        else asm volatile("cp.async.commit_group;" ::: "memory");   // keep group count uniform

        const int buf = kt % SNST;
        const uint32_t* sAw = smem + (size_t)buf * STGW;
        const uint32_t sAb = sbase + (uint32_t)(buf * STGW * 4);
        const uint32_t sBb = sAb + A_WORDS * 4;

        #pragma unroll
        for (int ks = 0; ks < 2; ks++) {       // 2 x k16
            uint32_t af[2][4], bf[8][2];
            #pragma unroll
            for (int mi = 0; mi < 2; mi++) {
                const int rb = wm * 32 + mi * 16;
                if constexpr (A_MK) {
                    af[mi][0] = sAw[(rb + g)     * APK + ks * 8 + tg];
                    af[mi][1] = sAw[(rb + 8 + g) * APK + ks * 8 + tg];
                    af[mi][2] = sAw[(rb + g)     * APK + ks * 8 + 4 + tg];
                    af[mi][3] = sAw[(rb + 8 + g) * APK + ks * 8 + 4 + tg];
                } else {
                    const uint32_t row = (uint32_t)(ks * 16 + (lane & 7) + (((lane >> 4) & 1) << 3));
                    const uint32_t col = (uint32_t)(rb + (((lane >> 3) & 1) << 3));
                    const uint32_t addr = sAb + row * (AKM * 4) + col * 2;
                    asm volatile("ldmatrix.sync.aligned.m8n8.x4.trans.shared.b16 {%0,%1,%2,%3}, [%4];"
                                 : "=r"(af[mi][0]), "=r"(af[mi][1]), "=r"(af[mi][2]), "=r"(af[mi][3])
                                 : "r"(addr));
                }
            }
            #pragma unroll
            for (int np = 0; np < 4; np++) {   // each x4 covers ni = 2np, 2np+1
                const uint32_t row = (uint32_t)(ks * 16 + (lane & 7) + (((lane >> 3) & 1) << 3));
                const uint32_t col = (uint32_t)(wn * 64 + np * 16 + (((lane >> 4) & 1) << 3));
                const uint32_t addr = sBb + row * (BKN * 4) + col * 2;
                asm volatile("ldmatrix.sync.aligned.m8n8.x4.trans.shared.b16 {%0,%1,%2,%3}, [%4];"
                             : "=r"(bf[2 * np][0]), "=r"(bf[2 * np][1]),
                               "=r"(bf[2 * np + 1][0]), "=r"(bf[2 * np + 1][1])
                             : "r"(addr));
            }
            #pragma unroll
            for (int mi = 0; mi < 2; mi++)
                #pragma unroll
                for (int ni = 0; ni < 8; ni++)
                    asm volatile(
                        "mma.sync.aligned.m16n8k16.row.col.f32.f16.f16.f32 "
                        "{%0,%1,%2,%3}, {%4,%5,%6,%7}, {%8,%9}, {%0,%1,%2,%3};\n"
                        : "+f"(acc[mi][ni][0]), "+f"(acc[mi][ni][1]),
                          "+f"(acc[mi][ni][2]), "+f"(acc[mi][ni][3])
                        : "r"(af[mi][0]), "r"(af[mi][1]), "r"(af[mi][2]), "r"(af[mi][3]),
                          "r"(bf[ni][0]), "r"(bf[ni][1]));
        }
    }

    __half* C = Cg + (long long)zo * cOut + (long long)zi * cIn;
    #pragma unroll
    for (int mi = 0; mi < 2; mi++) {
        const int r0 = m0g + wm * 32 + mi * 16 + g;
        #pragma unroll
        for (int ni = 0; ni < 8; ni++) {
            const int c0 = n0g + wn * 64 + ni * 8 + tg * 2;
            __half2 h0 = __floats2half2_rn(acc[mi][ni][0], acc[mi][ni][1]);
            __half2 h1 = __floats2half2_rn(acc[mi][ni][2], acc[mi][ni][3]);
            *reinterpret_cast<__half2*>(&C[(long long)r0 * ldc + c0]) = h0;
            *reinterpret_cast<__half2*>(&C[(long long)(r0 + 8) * ldc + c0]) = h1;
        }
    }
}

// ---------------- big GEMM (fp16 + LDSM, 256 threads — R9 proven) ----------------
#define TM 128
#define TN 256
#define HBK 64
#define NST 4
#define HKT 32                              // 2048 / 64
#define HPITCH 36                           // u32 per row (72 halves; 144B pitch)
#define A_WORDS3 (TM * HPITCH)              // 4608 u32
#define B_WORDS3 (TN * HPITCH)              // 9216 u32
#define STG_WORDS (A_WORDS3 + B_WORDS3)     // 13824 u32
#define BIG_SMEM (NST * STG_WORDS * 4)      // 221184 bytes

__global__ void __launch_bounds__(256) big_gemm_h(
    const __half* __restrict__ Z, const __half* __restrict__ W,
    const float* __restrict__ bias, const float* __restrict__ S,
    float* __restrict__ out)
{
    extern __shared__ uint32_t smem[];
    uint32_t sbase;
    asm("{ .reg .u64 t; cvta.to.shared.u64 t, %1; cvt.u32.u64 %0, t; }"
        : "=r"(sbase) : "l"(smem));

    const int tid  = threadIdx.x;
    const int warp = tid >> 5;
    const int lane = tid & 31;
    const int wm = warp & 1;        // 2 warps along M (64 rows each)
    const int wn = warp >> 1;       // 4 warps along N (64 cols each)
    const int g  = lane >> 2;
    const int tg = lane & 3;

    const int m0 = blockIdx.x * TM;
    const int n0 = blockIdx.y * TN;
    const __half* Ab = Z + (size_t)m0 * 2048;
    const __half* Bb = W + (size_t)n0 * 2048;

    const uint32_t aRow = (uint32_t)((lane & 7) + (lane & 8));
    const uint32_t aCol = (uint32_t)((lane >> 4) << 4);
    const uint32_t bRow = (uint32_t)((lane & 7) + ((lane >> 4) << 3));
    const uint32_t bCol = (uint32_t)((lane & 8) << 1);

    float acc[4][8][4];
    #pragma unroll
    for (int mi = 0; mi < 4; mi++)
        #pragma unroll
        for (int ni = 0; ni < 8; ni++)
            #pragma unroll
            for (int q = 0; q < 4; q++) acc[mi][ni][q] = 0.f;

    auto load_tile = [&](int stg, int kt) {
        const uint32_t sA = sbase + (uint32_t)stg * (STG_WORDS * 4);
        const uint32_t sB = sA + A_WORDS3 * 4;
        const __half* As = Ab + kt * HBK;
        const __half* Bs = Bb + kt * HBK;
        #pragma unroll
        for (int j = 0; j < 4; j++) {
            int idx = tid + j * 256;
            int r = idx >> 3, c = idx & 7;
            cp16(sA + (uint32_t)(r * (HPITCH * 4) + c * 16), As + (size_t)r * 2048 + c * 8);
        }
        #pragma unroll
        for (int j = 0; j < 8; j++) {
            int idx = tid + j * 256;
            int r = idx >> 3, c = idx & 7;
            cp16(sB + (uint32_t)(r * (HPITCH * 4) + c * 16), Bs + (size_t)r * 2048 + c * 8);
        }
    };

    #pragma unroll
    for (int s = 0; s < NST - 1; s++) {
        load_tile(s, s);
        asm volatile("cp.async.commit_group;" ::: "memory");
    }

    for (int kt = 0; kt < HKT; kt++) {
        asm volatile("cp.async.wait_group 2;" ::: "memory");
        __syncthreads();

        if (kt + NST - 1 < HKT) load_tile((kt + NST - 1) & (NST - 1), kt + NST - 1);
        asm volatile("cp.async.commit_group;" ::: "memory");

        const uint32_t sAb = sbase + (uint32_t)((kt & (NST - 1)) * (STG_WORDS * 4));
        const uint32_t sBb = sAb + A_WORDS3 * 4;

        #pragma unroll
        for (int ks = 0; ks < 4; ks++) {
            const uint32_t kbyte = (uint32_t)(ks * 32);
            uint32_t af[4][4], bf[8][2];
            #pragma unroll
            for (int mi = 0; mi < 4; mi++) {
                const uint32_t addr = sAb + (uint32_t)(wm * 64 + mi * 16 + aRow) * (HPITCH * 4)
                                    + kbyte + aCol;
                asm volatile("ldmatrix.sync.aligned.m8n8.x4.shared.b16 {%0,%1,%2,%3}, [%4];"
                             : "=r"(af[mi][0]), "=r"(af[mi][1]), "=r"(af[mi][2]), "=r"(af[mi][3])
                             : "r"(addr));
            }
            #pragma unroll
            for (int np = 0; np < 4; np++) {
                const uint32_t addr = sBb + (uint32_t)(wn * 64 + np * 16 + bRow) * (HPITCH * 4)
                                    + kbyte + bCol;
                asm volatile("ldmatrix.sync.aligned.m8n8.x4.shared.b16 {%0,%1,%2,%3}, [%4];"
                             : "=r"(bf[2 * np][0]), "=r"(bf[2 * np][1]),
                               "=r"(bf[2 * np + 1][0]), "=r"(bf[2 * np + 1][1])
                             : "r"(addr));
            }
            #pragma unroll
            for (int mi = 0; mi < 4; mi++)
                #pragma unroll
                for (int ni = 0; ni < 8; ni++)
                    asm volatile(
                        "mma.sync.aligned.m16n8k16.row.col.f32.f16.f16.f32 "
                        "{%0,%1,%2,%3}, {%4,%5,%6,%7}, {%8,%9}, {%0,%1,%2,%3};\n"
                        : "+f"(acc[mi][ni][0]), "+f"(acc[mi][ni][1]),
                          "+f"(acc[mi][ni][2]), "+f"(acc[mi][ni][3])
                        : "r"(af[mi][0]), "r"(af[mi][1]), "r"(af[mi][2]), "r"(af[mi][3]),
                          "r"(bf[ni][0]), "r"(bf[ni][1]));
        }
    }

    #pragma unroll
    for (int mi = 0; mi < 4; mi++) {
        const int r0 = m0 + wm * 64 + mi * 16 + g;
        const float s0 = S[r0], s1 = S[r0 + 8];
        #pragma unroll
        for (int ni = 0; ni < 8; ni++) {
            const int c0 = n0 + wn * 64 + ni * 8 + tg * 2;
            const float b0 = bias[c0], b1 = bias[c0 + 1];
            float2 v0 = make_float2(acc[mi][ni][0] + b0 * s0, acc[mi][ni][1] + b1 * s0);
            float2 v1 = make_float2(acc[mi][ni][2] + b0 * s1, acc[mi][ni][3] + b1 * s1);
            *reinterpret_cast<float2*>(&out[(size_t)r0 * 8192 + c0]) = v0;
            *reinterpret_cast<float2*>(&out[(size_t)(r0 + 8) * 8192 + c0]) = v1;
        }
    }
}

// ---------------- launch ----------------
extern "C" void kernel_launch(void* const* d_in, const int* in_sizes, int n_in,
                              void* d_out, int out_size)
{
    const float* x      = (const float*)d_in[0];  // (4,1024,2048)
    const float* cmb    = (const float*)d_in[1];  // (4,1024,4,512)
    const float* mask   = (const float*)d_in[2];  // (4,1024,4,512)
    const float* weight = (const float*)d_in[3];  // (8192,2048)
    const float* bias   = (const float*)d_in[4];  // (8192,)
    float* out = (float*)d_out;                   // (4,1024,8192)

    float *S;
    __half *xh, *mh, *ch, *Xd, *Zh, *Wh;
    cudaGetSymbolAddress((void**)&xh, g_xh);
    cudaGetSymbolAddress((void**)&mh, g_mh);
    cudaGetSymbolAddress((void**)&ch, g_ch);
    cudaGetSymbolAddress((void**)&Xd, g_Xd);
    cudaGetSymbolAddress((void**)&Zh, g_Zh);
    cudaGetSymbolAddress((void**)&Wh, g_Wh);
    cudaGetSymbolAddress((void**)&S,  g_S);

    prep_inputs<<<16896, 256>>>(cmb, mask, x, ch, mh, xh, S);
    permute_w_h<<<16384, 256>>>(weight, Wh);

    // Stage 1: Xd[b,e](512x512,half) = mask^T @ x-slice   (A half (k,m), B half (k,n))
    {
        const int smem1 = (32 * AKM + 32 * BKN) * 4 * SNST;   // 52224 B
        cudaFuncSetAttribute(gemm_h16<false>, cudaFuncAttributeMaxDynamicSharedMemorySize, smem1);
        dim3 grid(512 / 128, 512 / 128, 16);
        gemm_h16<false><<<grid, 256, smem1>>>(
            mh, xh, Xd, 1024, 2048, 2048, 512,
            2097152LL, 512LL, 2097152LL, 512LL,
            1048576LL, 262144LL, 4);
    }
    // Stage 2: Zh[b,:,e*512:](1024x512) = cmb @ Xd[b,e]   (A half (m,k), B half (k,n))
    {
        const int smem2 = (128 * APK + 32 * BKN) * 4 * SNST;  // 56832 B
        cudaFuncSetAttribute(gemm_h16<true>, cudaFuncAttributeMaxDynamicSharedMemorySize, smem2);
        dim3 grid(512 / 128, 1024 / 128, 16);
        gemm_h16<true><<<grid, 256, smem2>>>(
            ch, Xd, Zh, 512, 2048, 512, 2048,
            2097152LL, 512LL, 1048576LL, 262144LL,
            2097152LL, 512LL, 4);
    }
    // Stage 3: out = Zh(4096x2048) @ Wh^T(2048x8192) + bias (x) S   (fp16 MMA + LDSM)
    {
        cudaFuncSetAttribute(big_gemm_h, cudaFuncAttributeMaxDynamicSharedMemorySize, BIG_SMEM);
        dim3 grid(4096 / TM, 8192 / TN, 1);
        big_gemm_h<<<grid, 256, BIG_SMEM>>>(Zh, Wh, bias, S, out);
    }
}

// round 14
// speedup vs baseline: 1.5392x; 1.0008x over previous
#include <cuda_runtime.h>
#include <cuda_fp16.h>
#include <cstdint>
#include <cstddef>

// Problem: B=4, T=1024, E=4, C=512, i=512, IN=2048, OUT=8192
//   w[e,o,j] = weight_flat[e*4194304 + o*512 + j]   (torch-style reshape)
//   Xd[b,e] = mask[b,:,e,:]^T @ x[b,:,e*512:]        (fp16 MMA, half out)
//   Zh[b,:,e*512:] = cmb[b,:,e,:] @ Xd[b,e]          (fp16 MMA, half out)
//   out[b] = Zh[b] @ Wh^T + bias (x) rowsum(cmb)     (fp16 MMA, M=4096,N=8192,K=2048)

// ---------------- scratch (allocation-free rule) ----------------
static __device__ __half g_xh[4ull * 1024 * 2048];     // 8,388,608 halves
static __device__ __half g_mh[4ull * 1024 * 4 * 512];  // 8,388,608 halves
static __device__ __half g_ch[4ull * 1024 * 4 * 512];  // 8,388,608 halves
static __device__ __half g_Xd[4ull * 4 * 512 * 512];   // 4,194,304 halves
static __device__ __half g_Zh[4096ull * 2048];         // 8,388,608 halves
static __device__ __half g_Wh[8192ull * 2048];         // permuted half weight
static __device__ float  g_S [4 * 1024];

__device__ __forceinline__ uint2 f4_to_h4(float4 v) {
    __half2 h01 = __floats2half2_rn(v.x, v.y);
    __half2 h23 = __floats2half2_rn(v.z, v.w);
    uint2 w;
    w.x = *reinterpret_cast<uint32_t*>(&h01);
    w.y = *reinterpret_cast<uint32_t*>(&h23);
    return w;
}

// ------------- fused prep: cmb->half(+rowsum), mask->half, x->half, weight permute -------------
// blocks [0,512):        cmb rows (8 rows/block, 1 warp/row) convert + rowsum
// blocks [512,8704):     mask, 1024 elems/block (8,388,608 total)
// blocks [8704,16896):   x,    1024 elems/block (8,388,608 total)
// blocks [16896,33280):  weight permute, 1024 elems/block (16,777,216 total)
__global__ void prep_inputs(const float* __restrict__ cmb, const float* __restrict__ mask,
                            const float* __restrict__ x, const float* __restrict__ weight,
                            __half* __restrict__ ch, __half* __restrict__ mh,
                            __half* __restrict__ xh, __half* __restrict__ wh,
                            float* __restrict__ S)
{
    const int blk = blockIdx.x;
    if (blk < 512) {
        const int wid = threadIdx.x >> 5, lane = threadIdx.x & 31;
        const int row = blk * 8 + wid;
        const float4* src = reinterpret_cast<const float4*>(cmb + (size_t)row * 2048);
        uint2* dst = reinterpret_cast<uint2*>(ch + (size_t)row * 2048);
        float s = 0.f;
        #pragma unroll
        for (int it = 0; it < 16; it++) {
            int j = lane + it * 32;
            float4 v = src[j];
            s += (v.x + v.y) + (v.z + v.w);
            dst[j] = f4_to_h4(v);
        }
        #pragma unroll
        for (int o = 16; o; o >>= 1) s += __shfl_xor_sync(0xffffffffu, s, o);
        if (lane == 0) S[row] = s;
    } else if (blk < 8704) {
        size_t i = ((size_t)(blk - 512) * 256 + threadIdx.x) * 4;
        float4 v = *reinterpret_cast<const float4*>(mask + i);
        *reinterpret_cast<uint2*>(mh + i) = f4_to_h4(v);
    } else if (blk < 16896) {
        size_t i = ((size_t)(blk - 8704) * 256 + threadIdx.x) * 4;
        float4 v = *reinterpret_cast<const float4*>(x + i);
        *reinterpret_cast<uint2*>(xh + i) = f4_to_h4(v);
    } else {
        size_t idx = (size_t)(blk - 16896) * 256 + threadIdx.x;   // 4,194,304 threads
        int j4 = (int)(idx & 127);
        int o  = (int)((idx >> 7) & 8191);
        int e  = (int)(idx >> 20);
        float4 v = *reinterpret_cast<const float4*>(weight + (size_t)e * 4194304 + (size_t)o * 512 + j4 * 4);
        *reinterpret_cast<uint2*>(wh + (size_t)o * 2048 + e * 512 + j4 * 4) = f4_to_h4(v);
    }
}

__device__ __forceinline__ void cp16(uint32_t dst, const void* src) {
    asm volatile("cp.async.cg.shared.global [%0], [%1], 16;" :: "r"(dst), "l"(src));
}

// ---------------- fp16 GEMM (stages 1 & 2): all-half, 3-stage cp.async pipeline --------
#define SBK 32
#define APK 20
#define AKM 68
#define BKN 68
#define SNST 3

template <bool A_MK>
__global__ void __launch_bounds__(256, 2) gemm_h16(
    const __half* __restrict__ Ag, const __half* __restrict__ Bg, __half* __restrict__ Cg,
    int K, long long lda, long long ldb, long long ldc,
    long long aOut, long long aIn, long long bOut, long long bIn,
    long long cOut, long long cIn, int innerCount)
{
    constexpr int A_WORDS = A_MK ? 128 * APK : SBK * AKM;   // 2560 / 2176
    constexpr int B_WORDS = SBK * BKN;                      // 2176
    constexpr int STGW = A_WORDS + B_WORDS;
    extern __shared__ uint32_t smem[];
    uint32_t sbase;
    asm("{ .reg .u64 t; cvta.to.shared.u64 t, %1; cvt.u32.u64 %0, t; }" : "=r"(sbase) : "l"(smem));

    const int z  = blockIdx.z;
    const int zo = z / innerCount;
    const int zi = z - zo * innerCount;
    const __half* A = Ag + (long long)zo * aOut + (long long)zi * aIn;
    const __half* B = Bg + (long long)zo * bOut + (long long)zi * bIn;

    const int m0g = blockIdx.y * 128;
    const int n0g = blockIdx.x * 128;
    const int tid  = threadIdx.x;
    const int warp = tid >> 5;
    const int lane = tid & 31;
    const int wm = warp & 3;        // 4 warps along M, 32 rows each
    const int wn = warp >> 2;       // 2 warps along N, 64 cols each
    const int g  = lane >> 2;
    const int tg = lane & 3;

    float acc[2][8][4];
    #pragma unroll
    for (int mi = 0; mi < 2; mi++)
        #pragma unroll
        for (int ni = 0; ni < 8; ni++)
            #pragma unroll
            for (int q = 0; q < 4; q++) acc[mi][ni][q] = 0.f;

    const int KTl = K / SBK;

    auto load_tile = [&](int buf, int kt) {
        const int k0g = kt * SBK;
        const uint32_t aBase = sbase + (uint32_t)(buf * STGW * 4);
        const uint32_t bBase = aBase + A_WORDS * 4;
        if constexpr (A_MK) {          // (m,k): 128 rows x 4 chunks (16B) = 512
            #pragma unroll
            for (int j = 0; j < 2; j++) {
                int idx = tid + j * 256;
                int m = idx >> 2, c = idx & 3;
                cp16(aBase + (uint32_t)(m * (APK * 4) + c * 16),
                     A + (long long)(m0g + m) * lda + k0g + c * 8);
            }
        } else {                       // (k,m): 32 rows x 16 chunks = 512
            #pragma unroll
            for (int j = 0; j < 2; j++) {
                int idx = tid + j * 256;
                int k = idx >> 4, c = idx & 15;
                cp16(aBase + (uint32_t)(k * (AKM * 4) + c * 16),
                     A + (long long)(k0g + k) * lda + m0g + c * 8);
            }
        }
        #pragma unroll
        for (int j = 0; j < 2; j++) {  // B (k,n): 32 rows x 16 chunks = 512
            int idx = tid + j * 256;
            int k = idx >> 4, c = idx & 15;
            cp16(bBase + (uint32_t)(k * (BKN * 4) + c * 16),
                 B + (long long)(k0g + k) * ldb + n0g + c * 8);
        }
        asm volatile("cp.async.commit_group;" ::: "memory");
    };

    load_tile(0, 0);
    load_tile(1, 1);

    for (int kt = 0; kt < KTl; kt++) {
        asm volatile("cp.async.wait_group 1;" ::: "memory");
        __syncthreads();

        if (kt + 2 < KTl) load_tile((kt + 2) % SNST, kt + 2);
        else asm volatile("cp.async.commit_group;" ::: "memory");

        const int buf = kt % SNST;
        const uint32_t* sAw = smem + (size_t)buf * STGW;
        const uint32_t sAb = sbase + (uint32_t)(buf * STGW * 4);
        const uint32_t sBb = sAb + A_WORDS * 4;

        #pragma unroll
        for (int ks = 0; ks < 2; ks++) {
            uint32_t af[2][4], bf[8][2];
            #pragma unroll
            for (int mi = 0; mi < 2; mi++) {
                const int rb = wm * 32 + mi * 16;
                if constexpr (A_MK) {
                    af[mi][0] = sAw[(rb + g)     * APK + ks * 8 + tg];
                    af[mi][1] = sAw[(rb + 8 + g) * APK + ks * 8 + tg];
                    af[mi][2] = sAw[(rb + g)     * APK + ks * 8 + 4 + tg];
                    af[mi][3] = sAw[(rb + 8 + g) * APK + ks * 8 + 4 + tg];
                } else {
                    const uint32_t row = (uint32_t)(ks * 16 + (lane & 7) + (((lane >> 4) & 1) << 3));
                    const uint32_t col = (uint32_t)(rb + (((lane >> 3) & 1) << 3));
                    const uint32_t addr = sAb + row * (AKM * 4) + col * 2;
                    asm volatile("ldmatrix.sync.aligned.m8n8.x4.trans.shared.b16 {%0,%1,%2,%3}, [%4];"
                                 : "=r"(af[mi][0]), "=r"(af[mi][1]), "=r"(af[mi][2]), "=r"(af[mi][3])
                                 : "r"(addr));
                }
            }
            #pragma unroll
            for (int np = 0; np < 4; np++) {
                const uint32_t row = (uint32_t)(ks * 16 + (lane & 7) + (((lane >> 3) & 1) << 3));
                const uint32_t col = (uint32_t)(wn * 64 + np * 16 + (((lane >> 4) & 1) << 3));
                const uint32_t addr = sBb + row * (BKN * 4) + col * 2;
                asm volatile("ldmatrix.sync.aligned.m8n8.x4.trans.shared.b16 {%0,%1,%2,%3}, [%4];"
                             : "=r"(bf[2 * np][0]), "=r"(bf[2 * np][1]),
                               "=r"(bf[2 * np + 1][0]), "=r"(bf[2 * np + 1][1])
                             : "r"(addr));
            }
            #pragma unroll
            for (int mi = 0; mi < 2; mi++)
                #pragma unroll
                for (int ni = 0; ni < 8; ni++)
                    asm volatile(
                        "mma.sync.aligned.m16n8k16.row.col.f32.f16.f16.f32 "
                        "{%0,%1,%2,%3}, {%4,%5,%6,%7}, {%8,%9}, {%0,%1,%2,%3};\n"
                        : "+f"(acc[mi][ni][0]), "+f"(acc[mi][ni][1]),
                          "+f"(acc[mi][ni][2]), "+f"(acc[mi][ni][3])
                        : "r"(af[mi][0]), "r"(af[mi][1]), "r"(af[mi][2]), "r"(af[mi][3]),
                          "r"(bf[ni][0]), "r"(bf[ni][1]));
        }
    }

    __half* C = Cg + (long long)zo * cOut + (long long)zi * cIn;
    #pragma unroll
    for (int mi = 0; mi < 2; mi++) {
        const int r0 = m0g + wm * 32 + mi * 16 + g;
        #pragma unroll
        for (int ni = 0; ni < 8; ni++) {
            const int c0 = n0g + wn * 64 + ni * 8 + tg * 2;
            __half2 h0 = __floats2half2_rn(acc[mi][ni][0], acc[mi][ni][1]);
            __half2 h1 = __floats2half2_rn(acc[mi][ni][2], acc[mi][ni][3]);
            *reinterpret_cast<__half2*>(&C[(long long)r0 * ldc + c0]) = h0;
            *reinterpret_cast<__half2*>(&C[(long long)(r0 + 8) * ldc + c0]) = h1;
        }
    }
}

// ---------------- big GEMM (fp16 + LDSM + fragment double-buffer) ----------------
#define TM 128
#define TN 256
#define HBK 64
#define NST 4
#define HKT 32                              // 2048 / 64
#define HPITCH 36                           // u32 per row (72 halves; 144B pitch)
#define A_WORDS3 (TM * HPITCH)              // 4608 u32
#define B_WORDS3 (TN * HPITCH)              // 9216 u32
#define STG_WORDS (A_WORDS3 + B_WORDS3)     // 13824 u32
#define BIG_SMEM (NST * STG_WORDS * 4)      // 221184 bytes

__global__ void __launch_bounds__(256) big_gemm_h(
    const __half* __restrict__ Z, const __half* __restrict__ W,
    const float* __restrict__ bias, const float* __restrict__ S,
    float* __restrict__ out)
{
    extern __shared__ uint32_t smem[];
    uint32_t sbase;
    asm("{ .reg .u64 t; cvta.to.shared.u64 t, %1; cvt.u32.u64 %0, t; }"
        : "=r"(sbase) : "l"(smem));

    const int tid  = threadIdx.x;
    const int warp = tid >> 5;
    const int lane = tid & 31;
    const int wm = warp & 1;        // 2 warps along M (64 rows each)
    const int wn = warp >> 1;       // 4 warps along N (64 cols each)
    const int g  = lane >> 2;
    const int tg = lane & 3;

    const int m0 = blockIdx.x * TM;
    const int n0 = blockIdx.y * TN;
    const __half* Ab = Z + (size_t)m0 * 2048;
    const __half* Bb = W + (size_t)n0 * 2048;

    const uint32_t aRow = (uint32_t)((lane & 7) + (lane & 8));
    const uint32_t aCol = (uint32_t)((lane >> 4) << 4);
    const uint32_t bRow = (uint32_t)((lane & 7) + ((lane >> 4) << 3));
    const uint32_t bCol = (uint32_t)((lane & 8) << 1);

    float acc[4][8][4];
    #pragma unroll
    for (int mi = 0; mi < 4; mi++)
        #pragma unroll
        for (int ni = 0; ni < 8; ni++)
            #pragma unroll
            for (int q = 0; q < 4; q++) acc[mi][ni][q] = 0.f;

    auto load_tile = [&](int stg, int kt) {
        const uint32_t sA = sbase + (uint32_t)stg * (STG_WORDS * 4);
        const uint32_t sB = sA + A_WORDS3 * 4;
        const __half* As = Ab + kt * HBK;
        const __half* Bs = Bb + kt * HBK;
        #pragma unroll
        for (int j = 0; j < 4; j++) {
            int idx = tid + j * 256;
            int r = idx >> 3, c = idx & 7;
            cp16(sA + (uint32_t)(r * (HPITCH * 4) + c * 16), As + (size_t)r * 2048 + c * 8);
        }
        #pragma unroll
        for (int j = 0; j < 8; j++) {
            int idx = tid + j * 256;
            int r = idx >> 3, c = idx & 7;
            cp16(sB + (uint32_t)(r * (HPITCH * 4) + c * 16), Bs + (size_t)r * 2048 + c * 8);
        }
    };

    #pragma unroll
    for (int s = 0; s < NST - 1; s++) {
        load_tile(s, s);
        asm volatile("cp.async.commit_group;" ::: "memory");
    }

    uint32_t af[2][4][4], bf[2][8][2];

    for (int kt = 0; kt < HKT; kt++) {
        asm volatile("cp.async.wait_group 2;" ::: "memory");
        __syncthreads();

        if (kt + NST - 1 < HKT) load_tile((kt + NST - 1) & (NST - 1), kt + NST - 1);
        asm volatile("cp.async.commit_group;" ::: "memory");

        const uint32_t sAb = sbase + (uint32_t)((kt & (NST - 1)) * (STG_WORDS * 4));
        const uint32_t sBb = sAb + A_WORDS3 * 4;

        // fragment loader for k16-step ks into buffer pb
        auto load_frags = [&](int ks, int pb) {
            const uint32_t kbyte = (uint32_t)(ks * 32);
            #pragma unroll
            for (int mi = 0; mi < 4; mi++) {
                const uint32_t addr = sAb + (uint32_t)(wm * 64 + mi * 16 + aRow) * (HPITCH * 4)
                                    + kbyte + aCol;
                asm volatile("ldmatrix.sync.aligned.m8n8.x4.shared.b16 {%0,%1,%2,%3}, [%4];"
                             : "=r"(af[pb][mi][0]), "=r"(af[pb][mi][1]),
                               "=r"(af[pb][mi][2]), "=r"(af[pb][mi][3])
                             : "r"(addr));
            }
            #pragma unroll
            for (int np = 0; np < 4; np++) {
                const uint32_t addr = sBb + (uint32_t)(wn * 64 + np * 16 + bRow) * (HPITCH * 4)
                                    + kbyte + bCol;
                asm volatile("ldmatrix.sync.aligned.m8n8.x4.shared.b16 {%0,%1,%2,%3}, [%4];"
                             : "=r"(bf[pb][2 * np][0]), "=r"(bf[pb][2 * np][1]),
                               "=r"(bf[pb][2 * np + 1][0]), "=r"(bf[pb][2 * np + 1][1])
                             : "r"(addr));
            }
        };

        load_frags(0, 0);
        #pragma unroll
        for (int ks = 0; ks < 4; ks++) {
            const int cur = ks & 1;
            if (ks < 3) load_frags(ks + 1, cur ^ 1);
            #pragma unroll
            for (int mi = 0; mi < 4; mi++)
                #pragma unroll
                for (int ni = 0; ni < 8; ni++)
                    asm volatile(
                        "mma.sync.aligned.m16n8k16.row.col.f32.f16.f16.f32 "
                        "{%0,%1,%2,%3}, {%4,%5,%6,%7}, {%8,%9}, {%0,%1,%2,%3};\n"
                        : "+f"(acc[mi][ni][0]), "+f"(acc[mi][ni][1]),
                          "+f"(acc[mi][ni][2]), "+f"(acc[mi][ni][3])
                        : "r"(af[cur][mi][0]), "r"(af[cur][mi][1]),
                          "r"(af[cur][mi][2]), "r"(af[cur][mi][3]),
                          "r"(bf[cur][ni][0]), "r"(bf[cur][ni][1]));
        }
    }

    #pragma unroll
    for (int mi = 0; mi < 4; mi++) {
        const int r0 = m0 + wm * 64 + mi * 16 + g;
        const float s0 = S[r0], s1 = S[r0 + 8];
        #pragma unroll
        for (int ni = 0; ni < 8; ni++) {
            const int c0 = n0 + wn * 64 + ni * 8 + tg * 2;
            const float b0 = bias[c0], b1 = bias[c0 + 1];
            float2 v0 = make_float2(acc[mi][ni][0] + b0 * s0, acc[mi][ni][1] + b1 * s0);
            float2 v1 = make_float2(acc[mi][ni][2] + b0 * s1, acc[mi][ni][3] + b1 * s1);
            *reinterpret_cast<float2*>(&out[(size_t)r0 * 8192 + c0]) = v0;
            *reinterpret_cast<float2*>(&out[(size_t)(r0 + 8) * 8192 + c0]) = v1;
        }
    }
}

// ---------------- launch ----------------
extern "C" void kernel_launch(void* const* d_in, const int* in_sizes, int n_in,
                              void* d_out, int out_size)
{
    const float* x      = (const float*)d_in[0];  // (4,1024,2048)
    const float* cmb    = (const float*)d_in[1];  // (4,1024,4,512)
    const float* mask   = (const float*)d_in[2];  // (4,1024,4,512)
    const float* weight = (const float*)d_in[3];  // (8192,2048)
    const float* bias   = (const float*)d_in[4];  // (8192,)
    float* out = (float*)d_out;                   // (4,1024,8192)

    float *S;
    __half *xh, *mh, *ch, *Xd, *Zh, *Wh;
    cudaGetSymbolAddress((void**)&xh, g_xh);
    cudaGetSymbolAddress((void**)&mh, g_mh);
    cudaGetSymbolAddress((void**)&ch, g_ch);
    cudaGetSymbolAddress((void**)&Xd, g_Xd);
    cudaGetSymbolAddress((void**)&Zh, g_Zh);
    cudaGetSymbolAddress((void**)&Wh, g_Wh);
    cudaGetSymbolAddress((void**)&S,  g_S);

    prep_inputs<<<33280, 256>>>(cmb, mask, x, weight, ch, mh, xh, Wh, S);

    // Stage 1: Xd[b,e](512x512,half) = mask^T @ x-slice   (A half (k,m), B half (k,n))
    {
        const int smem1 = (32 * AKM + 32 * BKN) * 4 * SNST;   // 52224 B
        cudaFuncSetAttribute(gemm_h16<false>, cudaFuncAttributeMaxDynamicSharedMemorySize, smem1);
        dim3 grid(512 / 128, 512 / 128, 16);
        gemm_h16<false><<<grid, 256, smem1>>>(
            mh, xh, Xd, 1024, 2048, 2048, 512,
            2097152LL, 512LL, 2097152LL, 512LL,
            1048576LL, 262144LL, 4);
    }
    // Stage 2: Zh[b,:,e*512:](1024x512) = cmb @ Xd[b,e]   (A half (m,k), B half (k,n))
    {
        const int smem2 = (128 * APK + 32 * BKN) * 4 * SNST;  // 56832 B
        cudaFuncSetAttribute(gemm_h16<true>, cudaFuncAttributeMaxDynamicSharedMemorySize, smem2);
        dim3 grid(512 / 128, 1024 / 128, 16);
        gemm_h16<true><<<grid, 256, smem2>>>(
            ch, Xd, Zh, 512, 2048, 512, 2048,
            2097152LL, 512LL, 1048576LL, 262144LL,
            2097152LL, 512LL, 4);
    }
    // Stage 3: out = Zh(4096x2048) @ Wh^T(2048x8192) + bias (x) S
    {
        cudaFuncSetAttribute(big_gemm_h, cudaFuncAttributeMaxDynamicSharedMemorySize, BIG_SMEM);
        dim3 grid(4096 / TM, 8192 / TN, 1);
        big_gemm_h<<<grid, 256, BIG_SMEM>>>(Zh, Wh, bias, S, out);
    }
}

// round 15
// speedup vs baseline: 1.6499x; 1.0719x over previous
#include <cuda_runtime.h>
#include <cuda_fp16.h>
#include <cstdint>
#include <cstddef>

// Problem: B=4, T=1024, E=4, C=512, i=512, IN=2048, OUT=8192
//   w[e,o,j] = weight_flat[e*4194304 + o*512 + j]   (torch-style reshape)
//   Xd[b,e] = mask[b,:,e,:]^T @ x[b,:,e*512:]        (fp16 MMA, half out)
//   Zh[b,:,e*512:] = cmb[b,:,e,:] @ Xd[b,e]          (fp16 MMA, half out)
//   out[b] = Zh[b] @ Wh^T + bias (x) rowsum(cmb)     (fp16 MMA, M=4096,N=8192,K=2048)

// ---------------- scratch (allocation-free rule) ----------------
static __device__ __half g_xh[4ull * 1024 * 2048];     // 8,388,608 halves
static __device__ __half g_mh[4ull * 1024 * 4 * 512];  // 8,388,608 halves
static __device__ __half g_ch[4ull * 1024 * 4 * 512];  // 8,388,608 halves
static __device__ __half g_Xd[4ull * 4 * 512 * 512];   // 4,194,304 halves
static __device__ __half g_Zh[4096ull * 2048];         // 8,388,608 halves
static __device__ __half g_Wh[8192ull * 2048];         // permuted half weight
static __device__ float  g_S [4 * 1024];

__device__ __forceinline__ uint2 f4_to_h4(float4 v) {
    __half2 h01 = __floats2half2_rn(v.x, v.y);
    __half2 h23 = __floats2half2_rn(v.z, v.w);
    uint2 w;
    w.x = *reinterpret_cast<uint32_t*>(&h01);
    w.y = *reinterpret_cast<uint32_t*>(&h23);
    return w;
}

// ------------- fused prep: cmb->half(+rowsum), mask->half, x->half, weight permute -------------
__global__ void prep_inputs(const float* __restrict__ cmb, const float* __restrict__ mask,
                            const float* __restrict__ x, const float* __restrict__ weight,
                            __half* __restrict__ ch, __half* __restrict__ mh,
                            __half* __restrict__ xh, __half* __restrict__ wh,
                            float* __restrict__ S)
{
    const int blk = blockIdx.x;
    if (blk < 512) {
        const int wid = threadIdx.x >> 5, lane = threadIdx.x & 31;
        const int row = blk * 8 + wid;
        const float4* src = reinterpret_cast<const float4*>(cmb + (size_t)row * 2048);
        uint2* dst = reinterpret_cast<uint2*>(ch + (size_t)row * 2048);
        float s = 0.f;
        #pragma unroll
        for (int it = 0; it < 16; it++) {
            int j = lane + it * 32;
            float4 v = src[j];
            s += (v.x + v.y) + (v.z + v.w);
            dst[j] = f4_to_h4(v);
        }
        #pragma unroll
        for (int o = 16; o; o >>= 1) s += __shfl_xor_sync(0xffffffffu, s, o);
        if (lane == 0) S[row] = s;
    } else if (blk < 8704) {
        size_t i = ((size_t)(blk - 512) * 256 + threadIdx.x) * 4;
        float4 v = *reinterpret_cast<const float4*>(mask + i);
        *reinterpret_cast<uint2*>(mh + i) = f4_to_h4(v);
    } else if (blk < 16896) {
        size_t i = ((size_t)(blk - 8704) * 256 + threadIdx.x) * 4;
        float4 v = *reinterpret_cast<const float4*>(x + i);
        *reinterpret_cast<uint2*>(xh + i) = f4_to_h4(v);
    } else {
        size_t idx = (size_t)(blk - 16896) * 256 + threadIdx.x;   // 4,194,304 threads
        int j4 = (int)(idx & 127);
        int o  = (int)((idx >> 7) & 8191);
        int e  = (int)(idx >> 20);
        float4 v = *reinterpret_cast<const float4*>(weight + (size_t)e * 4194304 + (size_t)o * 512 + j4 * 4);
        *reinterpret_cast<uint2*>(wh + (size_t)o * 2048 + e * 512 + j4 * 4) = f4_to_h4(v);
    }
}

__device__ __forceinline__ void cp16(uint32_t dst, const void* src) {
    asm volatile("cp.async.cg.shared.global [%0], [%1], 16;" :: "r"(dst), "l"(src));
}

// ---------------- fp16 GEMM (stages 1 & 2): all-half, 3-stage cp.async pipeline --------
#define SBK 32
#define APK 20
#define AKM 68
#define BKN 68
#define SNST 3

template <bool A_MK>
__global__ void __launch_bounds__(256, 2) gemm_h16(
    const __half* __restrict__ Ag, const __half* __restrict__ Bg, __half* __restrict__ Cg,
    int K, long long lda, long long ldb, long long ldc,
    long long aOut, long long aIn, long long bOut, long long bIn,
    long long cOut, long long cIn, int innerCount)
{
    constexpr int A_WORDS = A_MK ? 128 * APK : SBK * AKM;   // 2560 / 2176
    constexpr int B_WORDS = SBK * BKN;                      // 2176
    constexpr int STGW = A_WORDS + B_WORDS;
    extern __shared__ uint32_t smem[];
    uint32_t sbase;
    asm("{ .reg .u64 t; cvta.to.shared.u64 t, %1; cvt.u32.u64 %0, t; }" : "=r"(sbase) : "l"(smem));

    const int z  = blockIdx.z;
    const int zo = z / innerCount;
    const int zi = z - zo * innerCount;
    const __half* A = Ag + (long long)zo * aOut + (long long)zi * aIn;
    const __half* B = Bg + (long long)zo * bOut + (long long)zi * bIn;

    const int m0g = blockIdx.y * 128;
    const int n0g = blockIdx.x * 128;
    const int tid  = threadIdx.x;
    const int warp = tid >> 5;
    const int lane = tid & 31;
    const int wm = warp & 3;        // 4 warps along M, 32 rows each
    const int wn = warp >> 2;       // 2 warps along N, 64 cols each
    const int g  = lane >> 2;
    const int tg = lane & 3;

    float acc[2][8][4];
    #pragma unroll
    for (int mi = 0; mi < 2; mi++)
        #pragma unroll
        for (int ni = 0; ni < 8; ni++)
            #pragma unroll
            for (int q = 0; q < 4; q++) acc[mi][ni][q] = 0.f;

    const int KTl = K / SBK;

    auto load_tile = [&](int buf, int kt) {
        const int k0g = kt * SBK;
        const uint32_t aBase = sbase + (uint32_t)(buf * STGW * 4);
        const uint32_t bBase = aBase + A_WORDS * 4;
        if constexpr (A_MK) {
            #pragma unroll
            for (int j = 0; j < 2; j++) {
                int idx = tid + j * 256;
                int m = idx >> 2, c = idx & 3;
                cp16(aBase + (uint32_t)(m * (APK * 4) + c * 16),
                     A + (long long)(m0g + m) * lda + k0g + c * 8);
            }
        } else {
            #pragma unroll
            for (int j = 0; j < 2; j++) {
                int idx = tid + j * 256;
                int k = idx >> 4, c = idx & 15;
                cp16(aBase + (uint32_t)(k * (AKM * 4) + c * 16),
                     A + (long long)(k0g + k) * lda + m0g + c * 8);
            }
        }
        #pragma unroll
        for (int j = 0; j < 2; j++) {
            int idx = tid + j * 256;
            int k = idx >> 4, c = idx & 15;
            cp16(bBase + (uint32_t)(k * (BKN * 4) + c * 16),
                 B + (long long)(k0g + k) * ldb + n0g + c * 8);
        }
        asm volatile("cp.async.commit_group;" ::: "memory");
    };

    load_tile(0, 0);
    load_tile(1, 1);

    for (int kt = 0; kt < KTl; kt++) {
        asm volatile("cp.async.wait_group 1;" ::: "memory");
        __syncthreads();

        if (kt + 2 < KTl) load_tile((kt + 2) % SNST, kt + 2);
        else asm volatile("cp.async.commit_group;" ::: "memory");

        const int buf = kt % SNST;
        const uint32_t* sAw = smem + (size_t)buf * STGW;
        const uint32_t sAb = sbase + (uint32_t)(buf * STGW * 4);
        const uint32_t sBb = sAb + A_WORDS * 4;

        #pragma unroll
        for (int ks = 0; ks < 2; ks++) {
            uint32_t af[2][4], bf[8][2];
            #pragma unroll
            for (int mi = 0; mi < 2; mi++) {
                const int rb = wm * 32 + mi * 16;
                if constexpr (A_MK) {
                    af[mi][0] = sAw[(rb + g)     * APK + ks * 8 + tg];
                    af[mi][1] = sAw[(rb + 8 + g) * APK + ks * 8 + tg];
                    af[mi][2] = sAw[(rb + g)     * APK + ks * 8 + 4 + tg];
                    af[mi][3] = sAw[(rb + 8 + g) * APK + ks * 8 + 4 + tg];
                } else {
                    const uint32_t row = (uint32_t)(ks * 16 + (lane & 7) + (((lane >> 4) & 1) << 3));
                    const uint32_t col = (uint32_t)(rb + (((lane >> 3) & 1) << 3));
                    const uint32_t addr = sAb + row * (AKM * 4) + col * 2;
                    asm volatile("ldmatrix.sync.aligned.m8n8.x4.trans.shared.b16 {%0,%1,%2,%3}, [%4];"
                                 : "=r"(af[mi][0]), "=r"(af[mi][1]), "=r"(af[mi][2]), "=r"(af[mi][3])
                                 : "r"(addr));
                }
            }
            #pragma unroll
            for (int np = 0; np < 4; np++) {
                const uint32_t row = (uint32_t)(ks * 16 + (lane & 7) + (((lane >> 3) & 1) << 3));
                const uint32_t col = (uint32_t)(wn * 64 + np * 16 + (((lane >> 4) & 1) << 3));
                const uint32_t addr = sBb + row * (BKN * 4) + col * 2;
                asm volatile("ldmatrix.sync.aligned.m8n8.x4.trans.shared.b16 {%0,%1,%2,%3}, [%4];"
                             : "=r"(bf[2 * np][0]), "=r"(bf[2 * np][1]),
                               "=r"(bf[2 * np + 1][0]), "=r"(bf[2 * np + 1][1])
                             : "r"(addr));
            }
            #pragma unroll
            for (int mi = 0; mi < 2; mi++)
                #pragma unroll
                for (int ni = 0; ni < 8; ni++)
                    asm volatile(
                        "mma.sync.aligned.m16n8k16.row.col.f32.f16.f16.f32 "
                        "{%0,%1,%2,%3}, {%4,%5,%6,%7}, {%8,%9}, {%0,%1,%2,%3};\n"
                        : "+f"(acc[mi][ni][0]), "+f"(acc[mi][ni][1]),
                          "+f"(acc[mi][ni][2]), "+f"(acc[mi][ni][3])
                        : "r"(af[mi][0]), "r"(af[mi][1]), "r"(af[mi][2]), "r"(af[mi][3]),
                          "r"(bf[ni][0]), "r"(bf[ni][1]));
        }
    }

    __half* C = Cg + (long long)zo * cOut + (long long)zi * cIn;
    #pragma unroll
    for (int mi = 0; mi < 2; mi++) {
        const int r0 = m0g + wm * 32 + mi * 16 + g;
        #pragma unroll
        for (int ni = 0; ni < 8; ni++) {
            const int c0 = n0g + wn * 64 + ni * 8 + tg * 2;
            __half2 h0 = __floats2half2_rn(acc[mi][ni][0], acc[mi][ni][1]);
            __half2 h1 = __floats2half2_rn(acc[mi][ni][2], acc[mi][ni][3]);
            *reinterpret_cast<__half2*>(&C[(long long)r0 * ldc + c0]) = h0;
            *reinterpret_cast<__half2*>(&C[(long long)(r0 + 8) * ldc + c0]) = h1;
        }
    }
}

// ---------------- big GEMM: CTA 128x128, BK=64, 2 CTAs/SM, warp tile 64x32 ----------------
#define TM 128
#define TN 128
#define HBK 64
#define NST 3
#define HKT 32                              // 2048 / 64
#define HPITCH 36                           // u32 per 64-half row (144B pitch)
#define A_WORDS3 (TM * HPITCH)              // 4608 u32
#define B_WORDS3 (TN * HPITCH)              // 4608 u32
#define STG_WORDS (A_WORDS3 + B_WORDS3)     // 9216 u32 = 36864 B
#define BIG_SMEM (NST * STG_WORDS * 4)      // 110592 B -> 2 CTAs/SM

__global__ void __launch_bounds__(256, 2) big_gemm_h(
    const __half* __restrict__ Z, const __half* __restrict__ W,
    const float* __restrict__ bias, const float* __restrict__ S,
    float* __restrict__ out)
{
    extern __shared__ uint32_t smem[];
    uint32_t sbase;
    asm("{ .reg .u64 t; cvta.to.shared.u64 t, %1; cvt.u32.u64 %0, t; }"
        : "=r"(sbase) : "l"(smem));

    const int tid  = threadIdx.x;
    const int warp = tid >> 5;
    const int lane = tid & 31;
    const int wm = warp & 1;        // 2 warps along M (64 rows each)
    const int wn = warp >> 1;       // 4 warps along N (32 cols each)
    const int g  = lane >> 2;
    const int tg = lane & 3;

    const int m0 = blockIdx.x * TM;      // x fastest: wave covers all M-tiles
    const int n0 = blockIdx.y * TN;
    const __half* Ab = Z + (size_t)m0 * 2048;
    const __half* Bb = W + (size_t)n0 * 2048;

    // validated LDSM lane mappings (non-trans, K-major tiles)
    const uint32_t aRow = (uint32_t)((lane & 7) + (lane & 8));
    const uint32_t aCol = (uint32_t)((lane >> 4) << 4);
    const uint32_t bRow = (uint32_t)((lane & 7) + ((lane >> 4) << 3));
    const uint32_t bCol = (uint32_t)((lane & 8) << 1);

    float acc[4][4][4];
    #pragma unroll
    for (int mi = 0; mi < 4; mi++)
        #pragma unroll
        for (int ni = 0; ni < 4; ni++)
            #pragma unroll
            for (int q = 0; q < 4; q++) acc[mi][ni][q] = 0.f;

    auto load_tile = [&](int stg, int kt) {
        const uint32_t sA = sbase + (uint32_t)stg * (STG_WORDS * 4);
        const uint32_t sB = sA + A_WORDS3 * 4;
        const __half* As = Ab + kt * HBK;
        const __half* Bs = Bb + kt * HBK;
        #pragma unroll
        for (int j = 0; j < 4; j++) {            // A: 128 rows x 8 chunks = 1024
            int idx = tid + j * 256;
            int r = idx >> 3, c = idx & 7;
            cp16(sA + (uint32_t)(r * (HPITCH * 4) + c * 16), As + (size_t)r * 2048 + c * 8);
        }
        #pragma unroll
        for (int j = 0; j < 4; j++) {            // B: 128 rows x 8 chunks = 1024
            int idx = tid + j * 256;
            int r = idx >> 3, c = idx & 7;
            cp16(sB + (uint32_t)(r * (HPITCH * 4) + c * 16), Bs + (size_t)r * 2048 + c * 8);
        }
        asm volatile("cp.async.commit_group;" ::: "memory");
    };

    // prologue: tiles 0,1 -> bufs 0,1
    load_tile(0, 0);
    load_tile(1, 1);

    for (int kt = 0; kt < HKT; kt++) {
        asm volatile("cp.async.wait_group 1;" ::: "memory");
        __syncthreads();

        if (kt + 2 < HKT) load_tile((kt + 2) % NST, kt + 2);
        else asm volatile("cp.async.commit_group;" ::: "memory");

        const int buf = kt % NST;
        const uint32_t sAb = sbase + (uint32_t)(buf * (STG_WORDS * 4));
        const uint32_t sBb = sAb + A_WORDS3 * 4;

        #pragma unroll
        for (int ks = 0; ks < 4; ks++) {
            const uint32_t kbyte = (uint32_t)(ks * 32);
            uint32_t af[4][4], bf[4][2];
            #pragma unroll
            for (int mi = 0; mi < 4; mi++) {
                const uint32_t addr = sAb + (uint32_t)(wm * 64 + mi * 16 + aRow) * (HPITCH * 4)
                                    + kbyte + aCol;
                asm volatile("ldmatrix.sync.aligned.m8n8.x4.shared.b16 {%0,%1,%2,%3}, [%4];"
                             : "=r"(af[mi][0]), "=r"(af[mi][1]), "=r"(af[mi][2]), "=r"(af[mi][3])
                             : "r"(addr));
            }
            #pragma unroll
            for (int np = 0; np < 2; np++) {     // covers ni = 2np, 2np+1
                const uint32_t addr = sBb + (uint32_t)(wn * 32 + np * 16 + bRow) * (HPITCH * 4)
                                    + kbyte + bCol;
                asm volatile("ldmatrix.sync.aligned.m8n8.x4.shared.b16 {%0,%1,%2,%3}, [%4];"
                             : "=r"(bf[2 * np][0]), "=r"(bf[2 * np][1]),
                               "=r"(bf[2 * np + 1][0]), "=r"(bf[2 * np + 1][1])
                             : "r"(addr));
            }
            #pragma unroll
            for (int mi = 0; mi < 4; mi++)
                #pragma unroll
                for (int ni = 0; ni < 4; ni++)
                    asm volatile(
                        "mma.sync.aligned.m16n8k16.row.col.f32.f16.f16.f32 "
                        "{%0,%1,%2,%3}, {%4,%5,%6,%7}, {%8,%9}, {%0,%1,%2,%3};\n"
                        : "+f"(acc[mi][ni][0]), "+f"(acc[mi][ni][1]),
                          "+f"(acc[mi][ni][2]), "+f"(acc[mi][ni][3])
                        : "r"(af[mi][0]), "r"(af[mi][1]), "r"(af[mi][2]), "r"(af[mi][3]),
                          "r"(bf[ni][0]), "r"(bf[ni][1]));
        }
    }

    // epilogue: out = acc + bias[n] * S[m]
    #pragma unroll
    for (int mi = 0; mi < 4; mi++) {
        const int r0 = m0 + wm * 64 + mi * 16 + g;
        const float s0 = S[r0], s1 = S[r0 + 8];
        #pragma unroll
        for (int ni = 0; ni < 4; ni++) {
            const int c0 = n0 + wn * 32 + ni * 8 + tg * 2;
            const float b0 = bias[c0], b1 = bias[c0 + 1];
            float2 v0 = make_float2(acc[mi][ni][0] + b0 * s0, acc[mi][ni][1] + b1 * s0);
            float2 v1 = make_float2(acc[mi][ni][2] + b0 * s1, acc[mi][ni][3] + b1 * s1);
            *reinterpret_cast<float2*>(&out[(size_t)r0 * 8192 + c0]) = v0;
            *reinterpret_cast<float2*>(&out[(size_t)(r0 + 8) * 8192 + c0]) = v1;
        }
    }
}

// ---------------- launch ----------------
extern "C" void kernel_launch(void* const* d_in, const int* in_sizes, int n_in,
                              void* d_out, int out_size)
{
    const float* x      = (const float*)d_in[0];  // (4,1024,2048)
    const float* cmb    = (const float*)d_in[1];  // (4,1024,4,512)
    const float* mask   = (const float*)d_in[2];  // (4,1024,4,512)
    const float* weight = (const float*)d_in[3];  // (8192,2048)
    const float* bias   = (const float*)d_in[4];  // (8192,)
    float* out = (float*)d_out;                   // (4,1024,8192)

    float *S;
    __half *xh, *mh, *ch, *Xd, *Zh, *Wh;
    cudaGetSymbolAddress((void**)&xh, g_xh);
    cudaGetSymbolAddress((void**)&mh, g_mh);
    cudaGetSymbolAddress((void**)&ch, g_ch);
    cudaGetSymbolAddress((void**)&Xd, g_Xd);
    cudaGetSymbolAddress((void**)&Zh, g_Zh);
    cudaGetSymbolAddress((void**)&Wh, g_Wh);
    cudaGetSymbolAddress((void**)&S,  g_S);

    prep_inputs<<<33280, 256>>>(cmb, mask, x, weight, ch, mh, xh, Wh, S);

    // Stage 1: Xd[b,e](512x512,half) = mask^T @ x-slice   (A half (k,m), B half (k,n))
    {
        const int smem1 = (32 * AKM + 32 * BKN) * 4 * SNST;   // 52224 B
        cudaFuncSetAttribute(gemm_h16<false>, cudaFuncAttributeMaxDynamicSharedMemorySize, smem1);
        dim3 grid(512 / 128, 512 / 128, 16);
        gemm_h16<false><<<grid, 256, smem1>>>(
            mh, xh, Xd, 1024, 2048, 2048, 512,
            2097152LL, 512LL, 2097152LL, 512LL,
            1048576LL, 262144LL, 4);
    }
    // Stage 2: Zh[b,:,e*512:](1024x512) = cmb @ Xd[b,e]   (A half (m,k), B half (k,n))
    {
        const int smem2 = (128 * APK + 32 * BKN) * 4 * SNST;  // 56832 B
        cudaFuncSetAttribute(gemm_h16<true>, cudaFuncAttributeMaxDynamicSharedMemorySize, smem2);
        dim3 grid(512 / 128, 1024 / 128, 16);
        gemm_h16<true><<<grid, 256, smem2>>>(
            ch, Xd, Zh, 512, 2048, 512, 2048,
            2097152LL, 512LL, 1048576LL, 262144LL,
            2097152LL, 512LL, 4);
    }
    // Stage 3: out = Zh(4096x2048) @ Wh^T(2048x8192) + bias (x) S   (2 CTAs/SM)
    {
        cudaFuncSetAttribute(big_gemm_h, cudaFuncAttributeMaxDynamicSharedMemorySize, BIG_SMEM);
        dim3 grid(4096 / TM, 8192 / TN, 1);
        big_gemm_h<<<grid, 256, BIG_SMEM>>>(Zh, Wh, bias, S, out);
    }
}

// round 16
// speedup vs baseline: 1.6668x; 1.0103x over previous
#include <cuda_runtime.h>
#include <cuda_fp16.h>
#include <cstdint>
#include <cstddef>

// Problem: B=4, T=1024, E=4, C=512, i=512, IN=2048, OUT=8192
//   w[e,o,j] = weight_flat[e*4194304 + o*512 + j]   (torch-style reshape)
//   Xd[b,e] = mask[b,:,e,:]^T @ x[b,:,e*512:]        (fp16 MMA, half out)
//   Zh[b,:,e*512:] = cmb[b,:,e,:] @ Xd[b,e]          (fp16 MMA, half out)
//   out[b] = Zh[b] @ Wh^T + bias (x) rowsum(cmb)     (fp16 MMA, M=4096,N=8192,K=2048)

// ---------------- scratch (allocation-free rule) ----------------
static __device__ __half g_xh[4ull * 1024 * 2048];     // 8,388,608 halves
static __device__ __half g_mh[4ull * 1024 * 4 * 512];  // 8,388,608 halves
static __device__ __half g_ch[4ull * 1024 * 4 * 512];  // 8,388,608 halves
static __device__ __half g_Xd[4ull * 4 * 512 * 512];   // 4,194,304 halves
static __device__ __half g_Zh[4096ull * 2048];         // 8,388,608 halves
static __device__ __half g_Wh[8192ull * 2048];         // permuted half weight
static __device__ float  g_S [4 * 1024];

__device__ __forceinline__ uint2 f4_to_h4(float4 v) {
    __half2 h01 = __floats2half2_rn(v.x, v.y);
    __half2 h23 = __floats2half2_rn(v.z, v.w);
    uint2 w;
    w.x = *reinterpret_cast<uint32_t*>(&h01);
    w.y = *reinterpret_cast<uint32_t*>(&h23);
    return w;
}

// ------------- fused prep: cmb->half(+rowsum), mask->half, x->half, weight permute -------------
__global__ void prep_inputs(const float* __restrict__ cmb, const float* __restrict__ mask,
                            const float* __restrict__ x, const float* __restrict__ weight,
                            __half* __restrict__ ch, __half* __restrict__ mh,
                            __half* __restrict__ xh, __half* __restrict__ wh,
                            float* __restrict__ S)
{
    const int blk = blockIdx.x;
    if (blk < 512) {
        const int wid = threadIdx.x >> 5, lane = threadIdx.x & 31;
        const int row = blk * 8 + wid;
        const float4* src = reinterpret_cast<const float4*>(cmb + (size_t)row * 2048);
        uint2* dst = reinterpret_cast<uint2*>(ch + (size_t)row * 2048);
        float s = 0.f;
        #pragma unroll
        for (int it = 0; it < 16; it++) {
            int j = lane + it * 32;
            float4 v = src[j];
            s += (v.x + v.y) + (v.z + v.w);
            dst[j] = f4_to_h4(v);
        }
        #pragma unroll
        for (int o = 16; o; o >>= 1) s += __shfl_xor_sync(0xffffffffu, s, o);
        if (lane == 0) S[row] = s;
    } else if (blk < 8704) {
        size_t i = ((size_t)(blk - 512) * 256 + threadIdx.x) * 4;
        float4 v = *reinterpret_cast<const float4*>(mask + i);
        *reinterpret_cast<uint2*>(mh + i) = f4_to_h4(v);
    } else if (blk < 16896) {
        size_t i = ((size_t)(blk - 8704) * 256 + threadIdx.x) * 4;
        float4 v = *reinterpret_cast<const float4*>(x + i);
        *reinterpret_cast<uint2*>(xh + i) = f4_to_h4(v);
    } else {
        size_t idx = (size_t)(blk - 16896) * 256 + threadIdx.x;   // 4,194,304 threads
        int j4 = (int)(idx & 127);
        int o  = (int)((idx >> 7) & 8191);
        int e  = (int)(idx >> 20);
        float4 v = *reinterpret_cast<const float4*>(weight + (size_t)e * 4194304 + (size_t)o * 512 + j4 * 4);
        *reinterpret_cast<uint2*>(wh + (size_t)o * 2048 + e * 512 + j4 * 4) = f4_to_h4(v);
    }
}

__device__ __forceinline__ void cp16(uint32_t dst, const void* src) {
    asm volatile("cp.async.cg.shared.global [%0], [%1], 16;" :: "r"(dst), "l"(src));
}

// ---------------- fp16 GEMM (stages 1 & 2): all-half, BK=64, 3-stage cp.async --------
// C[M,N](half) = A @ B, tiles 128x128x64, 8 warps (4M x 2N), warp tile 32x64.
//   A_MK=true : A half (m,k) k-contig -> smem (m,k) pitch 36 u32, direct LDS frags
//   A_MK=false: A half (k,m) m-contig -> smem (k,m) pitch 68 u32, ldmatrix.trans
//   B         : B half (k,n) n-contig -> smem (k,n) pitch 68 u32, ldmatrix.trans
#define SBK 64
#define APK 36      // u32 pitch, A (m,k) layout (72 halves = 64 + 8 pad)
#define AKM 68      // u32 pitch, A (k,m) layout (136 halves)
#define BKN 68      // u32 pitch, B (k,n) layout
#define SNST 3

template <bool A_MK>
__global__ void __launch_bounds__(256, 2) gemm_h16(
    const __half* __restrict__ Ag, const __half* __restrict__ Bg, __half* __restrict__ Cg,
    int K, long long lda, long long ldb, long long ldc,
    long long aOut, long long aIn, long long bOut, long long bIn,
    long long cOut, long long cIn, int innerCount)
{
    constexpr int A_WORDS = A_MK ? 128 * APK : SBK * AKM;   // 4608 / 4352
    constexpr int B_WORDS = SBK * BKN;                      // 4352
    constexpr int STGW = A_WORDS + B_WORDS;
    extern __shared__ uint32_t smem[];
    uint32_t sbase;
    asm("{ .reg .u64 t; cvta.to.shared.u64 t, %1; cvt.u32.u64 %0, t; }" : "=r"(sbase) : "l"(smem));

    const int z  = blockIdx.z;
    const int zo = z / innerCount;
    const int zi = z - zo * innerCount;
    const __half* A = Ag + (long long)zo * aOut + (long long)zi * aIn;
    const __half* B = Bg + (long long)zo * bOut + (long long)zi * bIn;

    const int m0g = blockIdx.y * 128;
    const int n0g = blockIdx.x * 128;
    const int tid  = threadIdx.x;
    const int warp = tid >> 5;
    const int lane = tid & 31;
    const int wm = warp & 3;        // 4 warps along M, 32 rows each
    const int wn = warp >> 2;       // 2 warps along N, 64 cols each
    const int g  = lane >> 2;
    const int tg = lane & 3;

    float acc[2][8][4];
    #pragma unroll
    for (int mi = 0; mi < 2; mi++)
        #pragma unroll
        for (int ni = 0; ni < 8; ni++)
            #pragma unroll
            for (int q = 0; q < 4; q++) acc[mi][ni][q] = 0.f;

    const int KTl = K / SBK;

    auto load_tile = [&](int buf, int kt) {
        const int k0g = kt * SBK;
        const uint32_t aBase = sbase + (uint32_t)(buf * STGW * 4);
        const uint32_t bBase = aBase + A_WORDS * 4;
        if constexpr (A_MK) {          // (m,k): 128 rows x 8 chunks (8 halves) = 1024
            #pragma unroll
            for (int j = 0; j < 4; j++) {
                int idx = tid + j * 256;
                int m = idx >> 3, c = idx & 7;
                cp16(aBase + (uint32_t)(m * (APK * 4) + c * 16),
                     A + (long long)m * lda + (m0g, 0, k0g + c * 8, (void)0, k0g + c * 8));
            }
        } else {                       // (k,m): 64 rows x 16 chunks = 1024
            #pragma unroll
            for (int j = 0; j < 4; j++) {
                int idx = tid + j * 256;
                int k = idx >> 4, c = idx & 15;
                cp16(aBase + (uint32_t)(k * (AKM * 4) + c * 16),
                     A + (long long)(k0g + k) * lda + m0g + c * 8);
            }
        }
        #pragma unroll
        for (int j = 0; j < 4; j++) {  // B (k,n): 64 rows x 16 chunks = 1024
            int idx = tid + j * 256;
            int k = idx >> 4, c = idx & 15;
            cp16(bBase + (uint32_t)(k * (BKN * 4) + c * 16),
                 B + (long long)(k0g + k) * ldb + n0g + c * 8);
        }
        asm volatile("cp.async.commit_group;" ::: "memory");
    };
    // NOTE: the A_MK branch above must address A[(m0g+m)*lda + k0g + c*8]; fixed below
    // by a correct lambda (the comma-expression placeholder is removed in real code).

    auto load_tile_fix = [&](int buf, int kt) {
        const int k0g = kt * SBK;
        const uint32_t aBase = sbase + (uint32_t)(buf * STGW * 4);
        const uint32_t bBase = aBase + A_WORDS * 4;
        if constexpr (A_MK) {
            #pragma unroll
            for (int j = 0; j < 4; j++) {
                int idx = tid + j * 256;
                int m = idx >> 3, c = idx & 7;
                cp16(aBase + (uint32_t)(m * (APK * 4) + c * 16),
                     A + (long long)(m0g + m) * lda + k0g + c * 8);
            }
        } else {
            #pragma unroll
            for (int j = 0; j < 4; j++) {
                int idx = tid + j * 256;
                int k = idx >> 4, c = idx & 15;
                cp16(aBase + (uint32_t)(k * (AKM * 4) + c * 16),
                     A + (long long)(k0g + k) * lda + m0g + c * 8);
            }
        }
        #pragma unroll
        for (int j = 0; j < 4; j++) {
            int idx = tid + j * 256;
            int k = idx >> 4, c = idx & 15;
            cp16(bBase + (uint32_t)(k * (BKN * 4) + c * 16),
                 B + (long long)(k0g + k) * ldb + n0g + c * 8);
        }
        asm volatile("cp.async.commit_group;" ::: "memory");
    };
    (void)load_tile;

    load_tile_fix(0, 0);
    load_tile_fix(1, 1);

    for (int kt = 0; kt < KTl; kt++) {
        asm volatile("cp.async.wait_group 1;" ::: "memory");
        __syncthreads();

        if (kt + 2 < KTl) load_tile_fix((kt + 2) % SNST, kt + 2);
        else asm volatile("cp.async.commit_group;" ::: "memory");

        const int buf = kt % SNST;
        const uint32_t* sAw = smem + (size_t)buf * STGW;
        const uint32_t sAb = sbase + (uint32_t)(buf * STGW * 4);
        const uint32_t sBb = sAb + A_WORDS * 4;

        #pragma unroll
        for (int ks = 0; ks < 4; ks++) {       // 4 x k16 per 64-deep tile
            uint32_t af[2][4], bf[8][2];
            #pragma unroll
            for (int mi = 0; mi < 2; mi++) {
                const int rb = wm * 32 + mi * 16;
                if constexpr (A_MK) {
                    af[mi][0] = sAw[(rb + g)     * APK + ks * 8 + tg];
                    af[mi][1] = sAw[(rb + 8 + g) * APK + ks * 8 + tg];
                    af[mi][2] = sAw[(rb + g)     * APK + ks * 8 + 4 + tg];
                    af[mi][3] = sAw[(rb + 8 + g) * APK + ks * 8 + 4 + tg];
                } else {
                    const uint32_t row = (uint32_t)(ks * 16 + (lane & 7) + (((lane >> 4) & 1) << 3));
                    const uint32_t col = (uint32_t)(rb + (((lane >> 3) & 1) << 3));
                    const uint32_t addr = sAb + row * (AKM * 4) + col * 2;
                    asm volatile("ldmatrix.sync.aligned.m8n8.x4.trans.shared.b16 {%0,%1,%2,%3}, [%4];"
                                 : "=r"(af[mi][0]), "=r"(af[mi][1]), "=r"(af[mi][2]), "=r"(af[mi][3])
                                 : "r"(addr));
                }
            }
            #pragma unroll
            for (int np = 0; np < 4; np++) {   // each x4 covers ni = 2np, 2np+1
                const uint32_t row = (uint32_t)(ks * 16 + (lane & 7) + (((lane >> 3) & 1) << 3));
                const uint32_t col = (uint32_t)(wn * 64 + np * 16 + (((lane >> 4) & 1) << 3));
                const uint32_t addr = sBb + row * (BKN * 4) + col * 2;
                asm volatile("ldmatrix.sync.aligned.m8n8.x4.trans.shared.b16 {%0,%1,%2,%3}, [%4];"
                             : "=r"(bf[2 * np][0]), "=r"(bf[2 * np][1]),
                               "=r"(bf[2 * np + 1][0]), "=r"(bf[2 * np + 1][1])
                             : "r"(addr));
            }
            #pragma unroll
            for (int mi = 0; mi < 2; mi++)
                #pragma unroll
                for (int ni = 0; ni < 8; ni++)
                    asm volatile(
                        "mma.sync.aligned.m16n8k16.row.col.f32.f16.f16.f32 "
                        "{%0,%1,%2,%3}, {%4,%5,%6,%7}, {%8,%9}, {%0,%1,%2,%3};\n"
                        : "+f"(acc[mi][ni][0]), "+f"(acc[mi][ni][1]),
                          "+f"(acc[mi][ni][2]), "+f"(acc[mi][ni][3])
                        : "r"(af[mi][0]), "r"(af[mi][1]), "r"(af[mi][2]), "r"(af[mi][3]),
                          "r"(bf[ni][0]), "r"(bf[ni][1]));
        }
    }

    __half* C = Cg + (long long)zo * cOut + (long long)zi * cIn;
    #pragma unroll
    for (int mi = 0; mi < 2; mi++) {
        const int r0 = m0g + wm * 32 + mi * 16 + g;
        #pragma unroll
        for (int ni = 0; ni < 8; ni++) {
            const int c0 = n0g + wn * 64 + ni * 8 + tg * 2;
            __half2 h0 = __floats2half2_rn(acc[mi][ni][0], acc[mi][ni][1]);
            __half2 h1 = __floats2half2_rn(acc[mi][ni][2], acc[mi][ni][3]);
            *reinterpret_cast<__half2*>(&C[(long long)r0 * ldc + c0]) = h0;
            *reinterpret_cast<__half2*>(&C[(long long)(r0 + 8) * ldc + c0]) = h1;
        }
    }
}

// ---------------- big GEMM: CTA 128x128, BK=64, 2 CTAs/SM, warp tile 64x32 (R15 proven) --
#define TM 128
#define TN 128
#define HBK 64
#define NST 3
#define HKT 32                              // 2048 / 64
#define HPITCH 36                           // u32 per 64-half row (144B pitch)
#define A_WORDS3 (TM * HPITCH)              // 4608 u32
#define B_WORDS3 (TN * HPITCH)              // 4608 u32
#define STG_WORDS (A_WORDS3 + B_WORDS3)     // 9216 u32 = 36864 B
#define BIG_SMEM (NST * STG_WORDS * 4)      // 110592 B -> 2 CTAs/SM

__global__ void __launch_bounds__(256, 2) big_gemm_h(
    const __half* __restrict__ Z, const __half* __restrict__ W,
    const float* __restrict__ bias, const float* __restrict__ S,
    float* __restrict__ out)
{
    extern __shared__ uint32_t smem[];
    uint32_t sbase;
    asm("{ .reg .u64 t; cvta.to.shared.u64 t, %1; cvt.u32.u64 %0, t; }"
        : "=r"(sbase) : "l"(smem));

    const int tid  = threadIdx.x;
    const int warp = tid >> 5;
    const int lane = tid & 31;
    const int wm = warp & 1;        // 2 warps along M (64 rows each)
    const int wn = warp >> 1;       // 4 warps along N (32 cols each)
    const int g  = lane >> 2;
    const int tg = lane & 3;

    const int m0 = blockIdx.x * TM;
    const int n0 = blockIdx.y * TN;
    const __half* Ab = Z + (size_t)m0 * 2048;
    const __half* Bb = W + (size_t)n0 * 2048;

    const uint32_t aRow = (uint32_t)((lane & 7) + (lane & 8));
    const uint32_t aCol = (uint32_t)((lane >> 4) << 4);
    const uint32_t bRow = (uint32_t)((lane & 7) + ((lane >> 4) << 3));
    const uint32_t bCol = (uint32_t)((lane & 8) << 1);

    float acc[4][4][4];
    #pragma unroll
    for (int mi = 0; mi < 4; mi++)
        #pragma unroll
        for (int ni = 0; ni < 4; ni++)
            #pragma unroll
            for (int q = 0; q < 4; q++) acc[mi][ni][q] = 0.f;

    auto load_tile = [&](int stg, int kt) {
        const uint32_t sA = sbase + (uint32_t)stg * (STG_WORDS * 4);
        const uint32_t sB = sA + A_WORDS3 * 4;
        const __half* As = Ab + kt * HBK;
        const __half* Bs = Bb + kt * HBK;
        #pragma unroll
        for (int j = 0; j < 4; j++) {
            int idx = tid + j * 256;
            int r = idx >> 3, c = idx & 7;
            cp16(sA + (uint32_t)(r * (HPITCH * 4) + c * 16), As + (size_t)r * 2048 + c * 8);
        }
        #pragma unroll
        for (int j = 0; j < 4; j++) {
            int idx = tid + j * 256;
            int r = idx >> 3, c = idx & 7;
            cp16(sB + (uint32_t)(r * (HPITCH * 4) + c * 16), Bs + (size_t)r * 2048 + c * 8);
        }
        asm volatile("cp.async.commit_group;" ::: "memory");
    };

    load_tile(0, 0);
    load_tile(1, 1);

    for (int kt = 0; kt < HKT; kt++) {
        asm volatile("cp.async.wait_group 1;" ::: "memory");
        __syncthreads();

        if (kt + 2 < HKT) load_tile((kt + 2) % NST, kt + 2);
        else asm volatile("cp.async.commit_group;" ::: "memory");

        const int buf = kt % NST;
        const uint32_t sAb = sbase + (uint32_t)(buf * (STG_WORDS * 4));
        const uint32_t sBb = sAb + A_WORDS3 * 4;

        #pragma unroll
        for (int ks = 0; ks < 4; ks++) {
            const uint32_t kbyte = (uint32_t)(ks * 32);
            uint32_t af[4][4], bf[4][2];
            #pragma unroll
            for (int mi = 0; mi < 4; mi++) {
                const uint32_t addr = sAb + (uint32_t)(wm * 64 + mi * 16 + aRow) * (HPITCH * 4)
                                    + kbyte + aCol;
                asm volatile("ldmatrix.sync.aligned.m8n8.x4.shared.b16 {%0,%1,%2,%3}, [%4];"
                             : "=r"(af[mi][0]), "=r"(af[mi][1]), "=r"(af[mi][2]), "=r"(af[mi][3])
                             : "r"(addr));
            }
            #pragma unroll
            for (int np = 0; np < 2; np++) {
                const uint32_t addr = sBb + (uint32_t)(wn * 32 + np * 16 + bRow) * (HPITCH * 4)
                                    + kbyte + bCol;
                asm volatile("ldmatrix.sync.aligned.m8n8.x4.shared.b16 {%0,%1,%2,%3}, [%4];"
                             : "=r"(bf[2 * np][0]), "=r"(bf[2 * np][1]),
                               "=r"(bf[2 * np + 1][0]), "=r"(bf[2 * np + 1][1])
                             : "r"(addr));
            }
            #pragma unroll
            for (int mi = 0; mi < 4; mi++)
                #pragma unroll
                for (int ni = 0; ni < 4; ni++)
                    asm volatile(
                        "mma.sync.aligned.m16n8k16.row.col.f32.f16.f16.f32 "
                        "{%0,%1,%2,%3}, {%4,%5,%6,%7}, {%8,%9}, {%0,%1,%2,%3};\n"
                        : "+f"(acc[mi][ni][0]), "+f"(acc[mi][ni][1]),
                          "+f"(acc[mi][ni][2]), "+f"(acc[mi][ni][3])
                        : "r"(af[mi][0]), "r"(af[mi][1]), "r"(af[mi][2]), "r"(af[mi][3]),
                          "r"(bf[ni][0]), "r"(bf[ni][1]));
        }
    }

    #pragma unroll
    for (int mi = 0; mi < 4; mi++) {
        const int r0 = m0 + wm * 64 + mi * 16 + g;
        const float s0 = S[r0], s1 = S[r0 + 8];
        #pragma unroll
        for (int ni = 0; ni < 4; ni++) {
            const int c0 = n0 + wn * 32 + ni * 8 + tg * 2;
            const float b0 = bias[c0], b1 = bias[c0 + 1];
            float2 v0 = make_float2(acc[mi][ni][0] + b0 * s0, acc[mi][ni][1] + b1 * s0);
            float2 v1 = make_float2(acc[mi][ni][2] + b0 * s1, acc[mi][ni][3] + b1 * s1);
            *reinterpret_cast<float2*>(&out[(size_t)r0 * 8192 + c0]) = v0;
            *reinterpret_cast<float2*>(&out[(size_t)(r0 + 8) * 8192 + c0]) = v1;
        }
    }
}

// ---------------- launch ----------------
extern "C" void kernel_launch(void* const* d_in, const int* in_sizes, int n_in,
                              void* d_out, int out_size)
{
    const float* x      = (const float*)d_in[0];  // (4,1024,2048)
    const float* cmb    = (const float*)d_in[1];  // (4,1024,4,512)
    const float* mask   = (const float*)d_in[2];  // (4,1024,4,512)
    const float* weight = (const float*)d_in[3];  // (8192,2048)
    const float* bias   = (const float*)d_in[4];  // (8192,)
    float* out = (float*)d_out;                   // (4,1024,8192)

    float *S;
    __half *xh, *mh, *ch, *Xd, *Zh, *Wh;
    cudaGetSymbolAddress((void**)&xh, g_xh);
    cudaGetSymbolAddress((void**)&mh, g_mh);
    cudaGetSymbolAddress((void**)&ch, g_ch);
    cudaGetSymbolAddress((void**)&Xd, g_Xd);
    cudaGetSymbolAddress((void**)&Zh, g_Zh);
    cudaGetSymbolAddress((void**)&Wh, g_Wh);
    cudaGetSymbolAddress((void**)&S,  g_S);

    prep_inputs<<<33280, 256>>>(cmb, mask, x, weight, ch, mh, xh, Wh, S);

    // Stage 1: Xd[b,e](512x512,half) = mask^T @ x-slice   (A half (k,m), B half (k,n))
    {
        const int smem1 = (64 * AKM + 64 * BKN) * 4 * SNST;   // 104448 B
        cudaFuncSetAttribute(gemm_h16<false>, cudaFuncAttributeMaxDynamicSharedMemorySize, smem1);
        dim3 grid(512 / 128, 512 / 128, 16);
        gemm_h16<false><<<grid, 256, smem1>>>(
            mh, xh, Xd, 1024, 2048, 2048, 512,
            2097152LL, 512LL, 2097152LL, 512LL,
            1048576LL, 262144LL, 4);
    }
    // Stage 2: Zh[b,:,e*512:](1024x512) = cmb @ Xd[b,e]   (A half (m,k), B half (k,n))
    {
        const int smem2 = (128 * APK + 64 * BKN) * 4 * SNST;  // 107520 B
        cudaFuncSetAttribute(gemm_h16<true>, cudaFuncAttributeMaxDynamicSharedMemorySize, smem2);
        dim3 grid(512 / 128, 1024 / 128, 16);
        gemm_h16<true><<<grid, 256, smem2>>>(
            ch, Xd, Zh, 512, 2048, 512, 2048,
            2097152LL, 512LL, 1048576LL, 262144LL,
            2097152LL, 512LL, 4);
    }
    // Stage 3: out = Zh(4096x2048) @ Wh^T(2048x8192) + bias (x) S   (2 CTAs/SM)
    {
        cudaFuncSetAttribute(big_gemm_h, cudaFuncAttributeMaxDynamicSharedMemorySize, BIG_SMEM);
        dim3 grid(4096 / TM, 8192 / TN, 1);
        big_gemm_h<<<grid, 256, BIG_SMEM>>>(Zh, Wh, bias, S, out);
    }
}